// round 8
// baseline (speedup 1.0000x reference)
#include <cuda_runtime.h>
#include <cuda_bf16.h>
#include <math_constants.h>
#include <cstdint>

#define BB 16
#define WW 2048
#define CC 512
#define NN (BB*WW*CC)

// ---------- scratch (no allocations allowed) ----------
__device__ float g_Xs[NN];                 // X_spatial [B,W,C] (64 MB)
__device__ float g_tt[BB*WW];              // temporal token mean
__device__ float g_invdeg[BB*CC];          // 1/in_deg
__device__ float g_degpart[BB*8*CC];       // partial column sums
__device__ uint2 g_Ap[NN/2];               // X packed (hi bf16x2, lo bf16x2) [b][m][kpair] (64 MB)
__device__ uint2 g_Bp[BB*CC*CC/2];         // norm-adj^T packed [b][n][kpair] (16 MB)

__device__ __forceinline__ float softplusf(float x) {
    return fmaxf(x, 0.f) + log1pf(expf(-fabsf(x)));
}

// pack two consecutive values as (hi bf16x2, lo bf16x2)
__device__ __forceinline__ uint2 bf16x3_pack(float v0, float v1) {
    __nv_bfloat16 h0 = __float2bfloat16(v0);
    __nv_bfloat16 h1 = __float2bfloat16(v1);
    float r0 = v0 - __bfloat162float(h0);
    float r1 = v1 - __bfloat162float(h1);
    __nv_bfloat16 l0 = __float2bfloat16(r0);
    __nv_bfloat16 l1 = __float2bfloat16(r1);
    uint2 p;
    p.x = (uint32_t)__bfloat16_as_ushort(h0) | ((uint32_t)__bfloat16_as_ushort(h1) << 16);
    p.y = (uint32_t)__bfloat16_as_ushort(l0) | ((uint32_t)__bfloat16_as_ushort(l1) << 16);
    return p;
}

__device__ __forceinline__ void mma_bf16(float* c,
                                         uint32_t a0, uint32_t a1, uint32_t a2, uint32_t a3,
                                         uint32_t b0, uint32_t b1) {
    asm volatile(
        "mma.sync.aligned.m16n8k16.row.col.f32.bf16.bf16.f32 "
        "{%0,%1,%2,%3},{%4,%5,%6,%7},{%8,%9},{%0,%1,%2,%3};\n"
        : "+f"(c[0]), "+f"(c[1]), "+f"(c[2]), "+f"(c[3])
        : "r"(a0), "r"(a1), "r"(a2), "r"(a3), "r"(b0), "r"(b1));
}

// ---------- K1a: partial column sums of relu(adj) ----------
__global__ void deg_partial_kernel(const float* __restrict__ adj) {
    int b = blockIdx.y, chunk = blockIdx.x;
    int i0 = chunk * 64;
    const float* A = adj + (size_t)b * CC * CC;
    for (int j = threadIdx.x; j < CC; j += blockDim.x) {
        float s = 0.f;
        #pragma unroll 8
        for (int i = 0; i < 64; i++)
            s += fmaxf(A[(size_t)(i0 + i) * CC + j], 0.f);
        g_degpart[(b * 8 + chunk) * CC + j] = s;
    }
}

// ---------- K1b: reduce + invert ----------
__global__ void invdeg_kernel() {
    int idx = blockIdx.x * blockDim.x + threadIdx.x;
    if (idx >= BB * CC) return;
    int b = idx / CC, j = idx % CC;
    float s = 0.f;
    #pragma unroll
    for (int c = 0; c < 8; c++) s += g_degpart[(b * 8 + c) * CC + j];
    g_invdeg[idx] = 1.0f / fmaxf(s, 1e-4f);
}

// ---------- K1c: pre-split X -> packed hi/lo planes ----------
__global__ void presplitX_kernel(const float* __restrict__ X) {
    size_t i = ((size_t)blockIdx.x * blockDim.x + threadIdx.x) * 4;
    float4 v = *(const float4*)(X + i);
    g_Ap[(i >> 1) + 0] = bf16x3_pack(v.x, v.y);
    g_Ap[(i >> 1) + 1] = bf16x3_pack(v.z, v.w);
}

// ---------- K1d: B = transpose(relu(adj)) * invdeg -> packed planes ----------
__global__ void presplitB_kernel(const float* __restrict__ adj) {
    __shared__ float t[32][33];
    int b = blockIdx.z;
    int i0 = blockIdx.y * 32, j0 = blockIdx.x * 32;
    int tx = threadIdx.x, ty = threadIdx.y;   // (32, 8)
    const float* A = adj + (size_t)b * CC * CC;
    #pragma unroll
    for (int r = 0; r < 4; r++) {
        int il = ty + r * 8;
        t[il][tx] = fmaxf(A[(size_t)(i0 + il) * CC + j0 + tx], 0.f);
    }
    __syncthreads();
    if (tx < 16) {
        #pragma unroll
        for (int r = 0; r < 4; r++) {
            int jl = ty + r * 8;
            int j = j0 + jl;
            float sc = g_invdeg[b * CC + j];
            float v0 = t[2 * tx][jl] * sc;
            float v1 = t[2 * tx + 1][jl] * sc;
            g_Bp[(((size_t)b * CC + j) * CC + i0) / 2 + tx] = bf16x3_pack(v0, v1);
        }
    }
}

// ---------- K2: 3xBF16 HMMA GEMM with cp.async double buffer ----------
#define BM 128
#define BN 128
#define BK 32
#define KP (BK / 2)           // 16 kpairs per chunk
#define SA 20                 // uint2 row stride (conflict-free LDS.64)
#define NCHUNK (CC / BK)      // 16
#define TILE_U2 (128 * SA)    // uint2 per tile
#define STAGE_U2 (2 * TILE_U2)
#define SMEM_GEMM (2 * STAGE_U2 * 8)   // 81920 B

__global__ void __launch_bounds__(256, 2) gemm_kernel() {
    extern __shared__ uint2 smem[];
    uint2* As[2] = { smem, smem + STAGE_U2 };
    uint2* Bs[2] = { smem + TILE_U2, smem + STAGE_U2 + TILE_U2 };

    int b = blockIdx.z, m0 = blockIdx.y * BM, n0 = blockIdx.x * BN;
    int tid = threadIdx.x;
    int lane = tid & 31, wid = tid >> 5;
    int quad = lane >> 2, tq = lane & 3;
    int wm = wid >> 1, wn = wid & 1;

    const uint2* Abase = g_Ap + (size_t)(b * WW + m0) * (CC / 2);
    const uint2* Bbase = g_Bp + ((size_t)b * CC + n0) * (CC / 2);

    float acc[2][8][4];
    #pragma unroll
    for (int am = 0; am < 2; am++)
        #pragma unroll
        for (int an = 0; an < 8; an++)
            #pragma unroll
            for (int q = 0; q < 4; q++) acc[am][an][q] = 0.f;

    // per-thread: 4 x 16B chunks for A, 4 for B per stage
    #define LOAD_STAGE(c, s) do { \
        int _kp0 = (c) * KP; \
        _Pragma("unroll") \
        for (int it = 0; it < 4; it++) { \
            int ch = tid * 4 + it;              /* 0..1023 */ \
            int row = ch >> 3, c16 = ch & 7;    /* 8 x 16B per row */ \
            uint32_t dA = (uint32_t)__cvta_generic_to_shared(&As[s][row * SA + c16 * 2]); \
            const uint2* sA = Abase + (size_t)row * (CC / 2) + _kp0 + c16 * 2; \
            asm volatile("cp.async.cg.shared.global [%0], [%1], 16;" \
                :: "r"(dA), "l"((unsigned long long)__cvta_generic_to_global((void*)sA)) : "memory"); \
            uint32_t dB = (uint32_t)__cvta_generic_to_shared(&Bs[s][row * SA + c16 * 2]); \
            const uint2* sB = Bbase + (size_t)row * (CC / 2) + _kp0 + c16 * 2; \
            asm volatile("cp.async.cg.shared.global [%0], [%1], 16;" \
                :: "r"(dB), "l"((unsigned long long)__cvta_generic_to_global((void*)sB)) : "memory"); \
        } \
        asm volatile("cp.async.commit_group;" ::: "memory"); \
    } while(0)

    LOAD_STAGE(0, 0);
    LOAD_STAGE(1, 1);

    for (int c = 0; c < NCHUNK; c++) {
        int s = c & 1;
        asm volatile("cp.async.wait_group 1;" ::: "memory");
        __syncthreads();

        #pragma unroll
        for (int ks = 0; ks < 2; ks++) {
            int kb = ks * 8;
            uint2 ah[2][4];
            #pragma unroll
            for (int am = 0; am < 2; am++) {
                int r0 = wm * 32 + am * 16 + quad;
                ah[am][0] = As[s][r0 * SA + kb + tq];
                ah[am][1] = As[s][(r0 + 8) * SA + kb + tq];
                ah[am][2] = As[s][r0 * SA + kb + 4 + tq];
                ah[am][3] = As[s][(r0 + 8) * SA + kb + 4 + tq];
            }
            #pragma unroll
            for (int an = 0; an < 8; an++) {
                int c0 = wn * 64 + an * 8 + quad;
                uint2 b0 = Bs[s][c0 * SA + kb + tq];
                uint2 b1 = Bs[s][c0 * SA + kb + 4 + tq];
                #pragma unroll
                for (int am = 0; am < 2; am++) {
                    float* cc = acc[am][an];
                    mma_bf16(cc, ah[am][0].x, ah[am][1].x, ah[am][2].x, ah[am][3].x, b0.x, b1.x);
                    mma_bf16(cc, ah[am][0].x, ah[am][1].x, ah[am][2].x, ah[am][3].x, b0.y, b1.y);
                    mma_bf16(cc, ah[am][0].y, ah[am][1].y, ah[am][2].y, ah[am][3].y, b0.x, b1.x);
                }
            }
        }
        __syncthreads();
        if (c + 2 < NCHUNK) LOAD_STAGE(c + 2, s);
    }

    // store (invdeg already folded into B)
    float* outp = g_Xs + (size_t)b * WW * CC;
    int cbase = n0 + wn * 64;
    #pragma unroll
    for (int am = 0; am < 2; am++) {
        int grow = m0 + wm * 32 + am * 16 + quad;
        #pragma unroll
        for (int an = 0; an < 8; an++) {
            int gc = cbase + an * 8 + tq * 2;
            *(float2*)(outp + (size_t)grow * CC + gc) = make_float2(acc[am][an][0], acc[am][an][1]);
            *(float2*)(outp + (size_t)(grow + 8) * CC + gc) = make_float2(acc[am][an][2], acc[am][an][3]);
        }
    }
    #undef LOAD_STAGE
}

// ---------- K3: temporal token = row mean over C ----------
__global__ void token_kernel() {
    int gwarp = (blockIdx.x * blockDim.x + threadIdx.x) >> 5;
    int lane = threadIdx.x & 31;
    if (gwarp >= BB * WW) return;
    const float4* row = (const float4*)(g_Xs + (size_t)gwarp * CC);
    float s = 0.f;
    #pragma unroll
    for (int q = 0; q < 4; q++) {
        float4 v = row[lane + 32 * q];
        s += v.x + v.y + v.z + v.w;
    }
    #pragma unroll
    for (int o = 16; o; o >>= 1) s += __shfl_xor_sync(0xffffffffu, s, o);
    if (lane == 0) g_tt[gwarp] = s * (1.0f / CC);
}

// ---------- K4: fused band-attention + epilogue ----------
#define TI 64
#define CJ 64
#define K2CAP 40
#define XR (TI + 2 * K2CAP)     // 144
#define NDTMAX (2 * K2CAP + 1)  // 81
#define SMEM_EPI ((XR * CJ + TI * NDTMAX + XR + TI) * 4)

__global__ __launch_bounds__(256)
void epilogue_kernel(const float* __restrict__ lt,
                     const float* __restrict__ wq, const float* __restrict__ bq,
                     const float* __restrict__ wk, const float* __restrict__ bk,
                     const float* __restrict__ wv, const float* __restrict__ bv,
                     const float* __restrict__ wmu, const float* __restrict__ bmu,
                     const float* __restrict__ wsig, const float* __restrict__ bsig,
                     const int* __restrict__ k1p, const int* __restrict__ k2p,
                     float* __restrict__ out) {
    extern __shared__ float esm[];
    float* sX  = esm;                 // [XR][CJ]
    float* sW  = esm + XR * CJ;       // [TI][NDTMAX]
    float* sTT = sW + TI * NDTMAX;    // [XR]
    float* sSac = sTT + XR;           // [TI]

    int b = blockIdx.z, i0 = blockIdx.y * TI, c0 = blockIdx.x * CJ;
    int k1 = k1p[0], k2 = k2p[0];
    float invt = 1.0f / (softplusf(lt[0]) + 1e-4f);
    float vwq = wq[0], vbq = bq[0], vwk = wk[0], vbk = bk[0];
    float vwv = wv[0], vbv = bv[0];
    float vwmu = wmu[0], vbmu = bmu[0], vws = wsig[0], vbs = bsig[0];
    int tid = threadIdx.x;
    float* muo = out;
    float* sgo = out + (size_t)NN;
    float* sco = out + 2 * (size_t)NN;

    if (k2 <= K2CAP) {
        int jlo = i0 - k2;
        int nrows = TI + 2 * k2;
        int ndt = 2 * k2 + 1;
        for (int idx = tid; idx < nrows * (CJ / 4); idx += 256) {
            int row = idx >> 4;
            int c4 = (idx & 15) * 4;
            int j = jlo + row;
            float4 v = make_float4(0.f, 0.f, 0.f, 0.f);
            if (j >= 0 && j < WW)
                v = *(const float4*)(g_Xs + (size_t)(b * WW + j) * CC + c0 + c4);
            *(float4*)&sX[row * CJ + c4] = v;
        }
        for (int idx = tid; idx < nrows; idx += 256) {
            int j = jlo + idx;
            sTT[idx] = (j >= 0 && j < WW) ? g_tt[b * WW + j] : 0.f;
        }
        __syncthreads();

        int lane = tid & 31, wid = tid >> 5;
        for (int r = wid; r < TI; r += 8) {
            int i = i0 + r;
            float qi = fmaf(vwq, sTT[r + k2], vbq);
            float m = -CUDART_INF_F;
            for (int p = lane; p < ndt; p += 32) {
                int dt = p - k2;
                int j = i + dt;
                bool valid = (abs(dt) >= k1) && (j >= 0) && (j < WW);
                float l = valid ? qi * fmaf(vwk, sTT[r + p], vbk) * invt : -CUDART_INF_F;
                sW[r * NDTMAX + p] = l;
                m = fmaxf(m, l);
            }
            #pragma unroll
            for (int o = 16; o; o >>= 1) m = fmaxf(m, __shfl_xor_sync(0xffffffffu, m, o));
            if (m == -CUDART_INF_F) {
                for (int p = lane; p < ndt; p += 32) sW[r * NDTMAX + p] = 0.f;
                __syncwarp();
                if (lane == 0) {
                    sW[r * NDTMAX + k2] = 1.0f / (1.f + 1e-6f);
                    sSac[r] = 1.0f / (1.f + 1e-6f);
                }
            } else {
                float zs = 0.f;
                for (int p = lane; p < ndt; p += 32) {
                    float e = expf(sW[r * NDTMAX + p] - m);
                    sW[r * NDTMAX + p] = e;
                    zs += e;
                }
                #pragma unroll
                for (int o = 16; o; o >>= 1) zs += __shfl_xor_sync(0xffffffffu, zs, o);
                float invz = 1.0f / zs;
                float s2 = 0.f;
                for (int p = lane; p < ndt; p += 32) {
                    float en = sW[r * NDTMAX + p] * invz;
                    sW[r * NDTMAX + p] = en;
                    s2 += en;
                }
                #pragma unroll
                for (int o = 16; o; o >>= 1) s2 += __shfl_xor_sync(0xffffffffu, s2, o);
                float invd = 1.0f / (s2 + 1e-6f);
                for (int p = lane; p < ndt; p += 32) sW[r * NDTMAX + p] *= invd;
                if (lane == 0) sSac[r] = s2 * invd;
            }
        }
        __syncthreads();

        int tx = tid & 15, ty = tid >> 4;
        int col = tx * 4;
        int pEnd1 = k2 - k1;
        int pStart2 = k2 + (k1 > 0 ? k1 : 1);
        #pragma unroll
        for (int rr = 0; rr < 4; rr++) {
            int r = ty * 4 + rr;
            int i = i0 + r;
            float4 a = make_float4(0.f, 0.f, 0.f, 0.f);
            for (int p = 0; p <= pEnd1; p++) {
                float w = sW[r * NDTMAX + p];
                float4 x = *(const float4*)&sX[(r + p) * CJ + col];
                a.x = fmaf(w, x.x, a.x);
                a.y = fmaf(w, x.y, a.y);
                a.z = fmaf(w, x.z, a.z);
                a.w = fmaf(w, x.w, a.w);
            }
            if (k1 > 0) {
                float w = sW[r * NDTMAX + k2];
                float4 x = *(const float4*)&sX[(r + k2) * CJ + col];
                a.x = fmaf(w, x.x, a.x);
                a.y = fmaf(w, x.y, a.y);
                a.z = fmaf(w, x.z, a.z);
                a.w = fmaf(w, x.w, a.w);
            }
            for (int p = pStart2; p <= 2 * k2; p++) {
                float w = sW[r * NDTMAX + p];
                float4 x = *(const float4*)&sX[(r + p) * CJ + col];
                a.x = fmaf(w, x.x, a.x);
                a.y = fmaf(w, x.y, a.y);
                a.z = fmaf(w, x.z, a.z);
                a.w = fmaf(w, x.w, a.w);
            }
            float sac = sSac[r];
            float4 xo = *(const float4*)&sX[(r + k2) * CJ + col];
            float4 xf, mu, sg;
            xf.x = fmaf(vwv, a.x, vbv * sac) + xo.x;
            xf.y = fmaf(vwv, a.y, vbv * sac) + xo.y;
            xf.z = fmaf(vwv, a.z, vbv * sac) + xo.z;
            xf.w = fmaf(vwv, a.w, vbv * sac) + xo.w;
            mu.x = fminf(fmaxf(fmaf(vwmu, xf.x, vbmu), -20.f), 20.f);
            mu.y = fminf(fmaxf(fmaf(vwmu, xf.y, vbmu), -20.f), 20.f);
            mu.z = fminf(fmaxf(fmaf(vwmu, xf.z, vbmu), -20.f), 20.f);
            mu.w = fminf(fmaxf(fmaf(vwmu, xf.w, vbmu), -20.f), 20.f);
            sg.x = softplusf(fmaf(vws, xf.x, vbs)) + 0.1f;
            sg.y = softplusf(fmaf(vws, xf.y, vbs)) + 0.1f;
            sg.z = softplusf(fmaf(vws, xf.z, vbs)) + 0.1f;
            sg.w = softplusf(fmaf(vws, xf.w, vbs)) + 0.1f;
            size_t o = (size_t)(b * WW + i) * CC + c0 + col;
            *(float4*)(muo + o) = mu;
            *(float4*)(sgo + o) = sg;
            *(float4*)(sco + o) = make_float4(sac, sac, sac, sac);
        }
    } else {
        // correct slow fallback for k2 > K2CAP
        int tx = tid & 15, ty = tid >> 4;
        int col = c0 + tx * 4;
        for (int rr = 0; rr < 4; rr++) {
            int r = ty * 4 + rr;
            int i = i0 + r;
            float qi = fmaf(vwq, g_tt[b * WW + i], vbq);
            float m = -CUDART_INF_F;
            for (int dt = -k2; dt <= k2; dt++) {
                int j = i + dt;
                if (abs(dt) < k1 || j < 0 || j >= WW) continue;
                float l = qi * fmaf(vwk, g_tt[b * WW + j], vbk) * invt;
                m = fmaxf(m, l);
            }
            float4 a = make_float4(0.f, 0.f, 0.f, 0.f);
            float sac = 1.0f / (1.f + 1e-6f);
            if (m == -CUDART_INF_F) {
                float w = sac;
                float4 xi = *(const float4*)(g_Xs + (size_t)(b * WW + i) * CC + col);
                a.x = w * xi.x; a.y = w * xi.y; a.z = w * xi.z; a.w = w * xi.w;
            } else {
                float Z = 0.f;
                for (int dt = -k2; dt <= k2; dt++) {
                    int j = i + dt;
                    if (abs(dt) < k1 || j < 0 || j >= WW) continue;
                    float l = qi * fmaf(vwk, g_tt[b * WW + j], vbk) * invt;
                    float e = expf(l - m);
                    Z += e;
                    float4 x = *(const float4*)(g_Xs + (size_t)(b * WW + j) * CC + col);
                    a.x = fmaf(e, x.x, a.x);
                    a.y = fmaf(e, x.y, a.y);
                    a.z = fmaf(e, x.z, a.z);
                    a.w = fmaf(e, x.w, a.w);
                }
                float s = 1.0f / (Z * (1.f + 1e-6f));
                a.x *= s; a.y *= s; a.z *= s; a.w *= s;
            }
            float4 xo = *(const float4*)(g_Xs + (size_t)(b * WW + i) * CC + col);
            float4 xf, mu, sg;
            xf.x = fmaf(vwv, a.x, vbv * sac) + xo.x;
            xf.y = fmaf(vwv, a.y, vbv * sac) + xo.y;
            xf.z = fmaf(vwv, a.z, vbv * sac) + xo.z;
            xf.w = fmaf(vwv, a.w, vbv * sac) + xo.w;
            mu.x = fminf(fmaxf(fmaf(vwmu, xf.x, vbmu), -20.f), 20.f);
            mu.y = fminf(fmaxf(fmaf(vwmu, xf.y, vbmu), -20.f), 20.f);
            mu.z = fminf(fmaxf(fmaf(vwmu, xf.z, vbmu), -20.f), 20.f);
            mu.w = fminf(fmaxf(fmaf(vwmu, xf.w, vbmu), -20.f), 20.f);
            sg.x = softplusf(fmaf(vws, xf.x, vbs)) + 0.1f;
            sg.y = softplusf(fmaf(vws, xf.y, vbs)) + 0.1f;
            sg.z = softplusf(fmaf(vws, xf.z, vbs)) + 0.1f;
            sg.w = softplusf(fmaf(vws, xf.w, vbs)) + 0.1f;
            size_t o = (size_t)(b * WW + i) * CC + c0 + col;
            *(float4*)(muo + o) = mu;
            *(float4*)(sgo + o) = sg;
            *(float4*)(sco + o) = make_float4(sac, sac, sac, sac);
        }
    }
}

// ---------- launch ----------
extern "C" void kernel_launch(void* const* d_in, const int* in_sizes, int n_in,
                              void* d_out, int out_size) {
    const float* X    = (const float*)d_in[0];
    const float* adj  = (const float*)d_in[1];
    const float* lt   = (const float*)d_in[2];
    const float* wq   = (const float*)d_in[3];
    const float* bq   = (const float*)d_in[4];
    const float* wk   = (const float*)d_in[5];
    const float* bk   = (const float*)d_in[6];
    const float* wv   = (const float*)d_in[7];
    const float* bv   = (const float*)d_in[8];
    const float* wmu  = (const float*)d_in[9];
    const float* bmu  = (const float*)d_in[10];
    const float* wsig = (const float*)d_in[11];
    const float* bsig = (const float*)d_in[12];
    const int*   k1p  = (const int*)d_in[13];
    const int*   k2p  = (const int*)d_in[14];
    float* out = (float*)d_out;

    cudaFuncSetAttribute(gemm_kernel,
                         cudaFuncAttributeMaxDynamicSharedMemorySize, SMEM_GEMM);
    cudaFuncSetAttribute(epilogue_kernel,
                         cudaFuncAttributeMaxDynamicSharedMemorySize, SMEM_EPI);

    dim3 g1(8, BB);
    deg_partial_kernel<<<g1, 256>>>(adj);
    invdeg_kernel<<<(BB * CC + 255) / 256, 256>>>();
    dim3 gb(16, 16, BB);
    presplitB_kernel<<<gb, dim3(32, 8)>>>(adj);
    presplitX_kernel<<<NN / 4 / 256, 256>>>(X);
    dim3 g2(CC / BN, WW / BM, BB);
    gemm_kernel<<<g2, 256, SMEM_GEMM>>>();
    token_kernel<<<(BB * WW) / 8, 256>>>();
    dim3 g5(CC / CJ, WW / TI, BB);
    epilogue_kernel<<<g5, 256, SMEM_EPI>>>(lt, wq, bq, wk, bk, wv, bv, wmu, bmu, wsig, bsig,
                                           k1p, k2p, out);
}

// round 11
// speedup vs baseline: 1.0534x; 1.0534x over previous
#include <cuda_runtime.h>
#include <cuda_bf16.h>
#include <math_constants.h>
#include <cstdint>

#define BB 16
#define WW 2048
#define CC 512
#define NN (BB*WW*CC)

// ---------- scratch (no allocations allowed) ----------
__device__ float g_Xs[NN];                 // X_spatial [B,W,C] (64 MB)
__device__ float g_ttp[8*BB*WW];           // partial row sums (8 planes)
__device__ float g_degpart[BB*8*CC];       // partial column sums
__device__ uint2 g_Ap[NN/2];               // X packed (hi bf16x2, lo bf16x2)
__device__ uint2 g_Bp[BB*CC*CC/2];         // norm-adj^T packed [b][n][kpair]

__device__ __forceinline__ float softplusf(float x) {
    return fmaxf(x, 0.f) + log1pf(expf(-fabsf(x)));
}

__device__ __forceinline__ uint2 bf16x3_pack(float v0, float v1) {
    __nv_bfloat16 h0 = __float2bfloat16(v0);
    __nv_bfloat16 h1 = __float2bfloat16(v1);
    float r0 = v0 - __bfloat162float(h0);
    float r1 = v1 - __bfloat162float(h1);
    __nv_bfloat16 l0 = __float2bfloat16(r0);
    __nv_bfloat16 l1 = __float2bfloat16(r1);
    uint2 p;
    p.x = (uint32_t)__bfloat16_as_ushort(h0) | ((uint32_t)__bfloat16_as_ushort(h1) << 16);
    p.y = (uint32_t)__bfloat16_as_ushort(l0) | ((uint32_t)__bfloat16_as_ushort(l1) << 16);
    return p;
}

__device__ __forceinline__ void mma_bf16(float* c,
                                         uint32_t a0, uint32_t a1, uint32_t a2, uint32_t a3,
                                         uint32_t b0, uint32_t b1) {
    asm volatile(
        "mma.sync.aligned.m16n8k16.row.col.f32.bf16.bf16.f32 "
        "{%0,%1,%2,%3},{%4,%5,%6,%7},{%8,%9},{%0,%1,%2,%3};\n"
        : "+f"(c[0]), "+f"(c[1]), "+f"(c[2]), "+f"(c[3])
        : "r"(a0), "r"(a1), "r"(a2), "r"(a3), "r"(b0), "r"(b1));
}

// ---------- K1: pre-split X -> packed hi/lo planes ----------
__global__ void presplitX_kernel(const float* __restrict__ X) {
    size_t i = ((size_t)blockIdx.x * blockDim.x + threadIdx.x) * 4;
    float4 v = *(const float4*)(X + i);
    g_Ap[(i >> 1) + 0] = bf16x3_pack(v.x, v.y);
    g_Ap[(i >> 1) + 1] = bf16x3_pack(v.z, v.w);
}

// ---------- K2: partial column sums of relu(adj) ----------
__global__ void deg_partial_kernel(const float* __restrict__ adj) {
    int b = blockIdx.y, chunk = blockIdx.x;
    int i0 = chunk * 64;
    const float* A = adj + (size_t)b * CC * CC;
    for (int j = threadIdx.x; j < CC; j += blockDim.x) {
        float s = 0.f;
        #pragma unroll 8
        for (int i = 0; i < 64; i++)
            s += fmaxf(A[(size_t)(i0 + i) * CC + j], 0.f);
        g_degpart[(b * 8 + chunk) * CC + j] = s;
    }
}

// ---------- K3: B = transpose(relu(adj)) * invdeg -> packed planes ----------
// (inline degree reduce; invdeg kernel eliminated)
__global__ void presplitB_kernel(const float* __restrict__ adj) {
    __shared__ float t[32][33];
    __shared__ float sdeg[32];
    int b = blockIdx.z;
    int i0 = blockIdx.y * 32, j0 = blockIdx.x * 32;
    int tx = threadIdx.x, ty = threadIdx.y;   // (32, 8)
    const float* A = adj + (size_t)b * CC * CC;
    if (ty == 0) {
        float s = 0.f;
        #pragma unroll
        for (int c = 0; c < 8; c++) s += g_degpart[(b * 8 + c) * CC + j0 + tx];
        sdeg[tx] = 1.0f / fmaxf(s, 1e-4f);
    }
    #pragma unroll
    for (int r = 0; r < 4; r++) {
        int il = ty + r * 8;
        t[il][tx] = fmaxf(A[(size_t)(i0 + il) * CC + j0 + tx], 0.f);
    }
    __syncthreads();
    if (tx < 16) {
        #pragma unroll
        for (int r = 0; r < 4; r++) {
            int jl = ty + r * 8;
            int j = j0 + jl;
            float sc = sdeg[jl];
            float v0 = t[2 * tx][jl] * sc;
            float v1 = t[2 * tx + 1][jl] * sc;
            g_Bp[(((size_t)b * CC + j) * CC + i0) / 2 + tx] = bf16x3_pack(v0, v1);
        }
    }
}

// ---------- K4: 3xBF16 HMMA GEMM + fused row-sum partials ----------
#define BM 128
#define BN 128
#define BK 32
#define KP (BK / 2)
#define SA 20
#define NCHUNK (CC / BK)
#define TILE_U2 (128 * SA)
#define STAGE_U2 (2 * TILE_U2)
#define SMEM_GEMM (2 * STAGE_U2 * 8)

__global__ void __launch_bounds__(256, 2) gemm_kernel() {
    extern __shared__ uint2 smem[];
    uint2* As[2] = { smem, smem + STAGE_U2 };
    uint2* Bs[2] = { smem + TILE_U2, smem + STAGE_U2 + TILE_U2 };

    int b = blockIdx.z, m0 = blockIdx.y * BM, n0 = blockIdx.x * BN;
    int tid = threadIdx.x;
    int lane = tid & 31, wid = tid >> 5;
    int quad = lane >> 2, tq = lane & 3;
    int wm = wid >> 1, wn = wid & 1;

    const uint2* Abase = g_Ap + (size_t)(b * WW + m0) * (CC / 2);
    const uint2* Bbase = g_Bp + ((size_t)b * CC + n0) * (CC / 2);

    float acc[2][8][4];
    #pragma unroll
    for (int am = 0; am < 2; am++)
        #pragma unroll
        for (int an = 0; an < 8; an++)
            #pragma unroll
            for (int q = 0; q < 4; q++) acc[am][an][q] = 0.f;

    #define LOAD_STAGE(c, s) do { \
        int _kp0 = (c) * KP; \
        _Pragma("unroll") \
        for (int it = 0; it < 4; it++) { \
            int ch = tid * 4 + it; \
            int row = ch >> 3, c16 = ch & 7; \
            uint32_t dA = (uint32_t)__cvta_generic_to_shared(&As[s][row * SA + c16 * 2]); \
            const uint2* sA = Abase + (size_t)row * (CC / 2) + _kp0 + c16 * 2; \
            asm volatile("cp.async.cg.shared.global [%0], [%1], 16;" \
                :: "r"(dA), "l"((unsigned long long)__cvta_generic_to_global((void*)sA)) : "memory"); \
            uint32_t dB = (uint32_t)__cvta_generic_to_shared(&Bs[s][row * SA + c16 * 2]); \
            const uint2* sB = Bbase + (size_t)row * (CC / 2) + _kp0 + c16 * 2; \
            asm volatile("cp.async.cg.shared.global [%0], [%1], 16;" \
                :: "r"(dB), "l"((unsigned long long)__cvta_generic_to_global((void*)sB)) : "memory"); \
        } \
        asm volatile("cp.async.commit_group;" ::: "memory"); \
    } while(0)

    LOAD_STAGE(0, 0);
    LOAD_STAGE(1, 1);

    for (int c = 0; c < NCHUNK; c++) {
        int s = c & 1;
        asm volatile("cp.async.wait_group 1;" ::: "memory");
        __syncthreads();

        #pragma unroll
        for (int ks = 0; ks < 2; ks++) {
            int kb = ks * 8;
            uint2 ah[2][4];
            #pragma unroll
            for (int am = 0; am < 2; am++) {
                int r0 = wm * 32 + am * 16 + quad;
                ah[am][0] = As[s][r0 * SA + kb + tq];
                ah[am][1] = As[s][(r0 + 8) * SA + kb + tq];
                ah[am][2] = As[s][r0 * SA + kb + 4 + tq];
                ah[am][3] = As[s][(r0 + 8) * SA + kb + 4 + tq];
            }
            #pragma unroll
            for (int an = 0; an < 8; an++) {
                int c0 = wn * 64 + an * 8 + quad;
                uint2 b0 = Bs[s][c0 * SA + kb + tq];
                uint2 b1 = Bs[s][c0 * SA + kb + 4 + tq];
                #pragma unroll
                for (int am = 0; am < 2; am++) {
                    float* cc = acc[am][an];
                    mma_bf16(cc, ah[am][0].x, ah[am][1].x, ah[am][2].x, ah[am][3].x, b0.x, b1.x);
                    mma_bf16(cc, ah[am][0].x, ah[am][1].x, ah[am][2].x, ah[am][3].x, b0.y, b1.y);
                    mma_bf16(cc, ah[am][0].y, ah[am][1].y, ah[am][2].y, ah[am][3].y, b0.x, b1.x);
                }
            }
        }
        __syncthreads();
        if (c + 2 < NCHUNK) LOAD_STAGE(c + 2, s);
    }

    // store (invdeg already folded into B)
    float* outp = g_Xs + (size_t)b * WW * CC;
    int cbase = n0 + wn * 64;
    #pragma unroll
    for (int am = 0; am < 2; am++) {
        int grow = m0 + wm * 32 + am * 16 + quad;
        #pragma unroll
        for (int an = 0; an < 8; an++) {
            int gc = cbase + an * 8 + tq * 2;
            *(float2*)(outp + (size_t)grow * CC + gc) = make_float2(acc[am][an][0], acc[am][an][1]);
            *(float2*)(outp + (size_t)(grow + 8) * CC + gc) = make_float2(acc[am][an][2], acc[am][an][3]);
        }
    }

    // fused partial row sums (replaces token_kernel); deterministic, no atomics
    float rs00 = 0.f, rs01 = 0.f, rs10 = 0.f, rs11 = 0.f;
    #pragma unroll
    for (int an = 0; an < 8; an++) {
        rs00 += acc[0][an][0] + acc[0][an][1];
        rs01 += acc[0][an][2] + acc[0][an][3];
        rs10 += acc[1][an][0] + acc[1][an][1];
        rs11 += acc[1][an][2] + acc[1][an][3];
    }
    #pragma unroll
    for (int o = 1; o <= 2; o <<= 1) {
        rs00 += __shfl_xor_sync(0xffffffffu, rs00, o);
        rs01 += __shfl_xor_sync(0xffffffffu, rs01, o);
        rs10 += __shfl_xor_sync(0xffffffffu, rs10, o);
        rs11 += __shfl_xor_sync(0xffffffffu, rs11, o);
    }
    if (tq == 0) {
        size_t pl = (size_t)(blockIdx.x * 2 + wn) * (BB * WW) + (size_t)b * WW;
        int r0w = m0 + wm * 32 + quad;
        const float inv = 1.0f / CC;
        g_ttp[pl + r0w]      = rs00 * inv;
        g_ttp[pl + r0w + 8]  = rs01 * inv;
        g_ttp[pl + r0w + 16] = rs10 * inv;
        g_ttp[pl + r0w + 24] = rs11 * inv;
    }
    #undef LOAD_STAGE
}

// ---------- K5: fused band-attention + epilogue ----------
#define TI 64
#define CJ 64
#define K2CAP 40
#define XR (TI + 2 * K2CAP)     // 144
#define NDTMAX (2 * K2CAP + 1)  // 81
#define SMEM_EPI ((XR * CJ + TI * NDTMAX + XR + TI) * 4)

__device__ __forceinline__ void fma4(float4& a, float w, const float4& x) {
    a.x = fmaf(w, x.x, a.x);
    a.y = fmaf(w, x.y, a.y);
    a.z = fmaf(w, x.z, a.z);
    a.w = fmaf(w, x.w, a.w);
}

// banded accumulate for one segment p in [plo, phi], 4 consecutive rows r0..r0+3
__device__ __forceinline__ void band_seg(const float* __restrict__ sX,
                                         const float* __restrict__ sW,
                                         int r0, int col, int plo, int phi,
                                         float4* a) {
    if (phi < plo) return;
    if (phi - plo >= 3) {
        #pragma unroll
        for (int e = 0; e < 3; e++) {           // head
            int t = plo + e;
            float4 x = *(const float4*)&sX[(r0 + t) * CJ + col];
            #pragma unroll
            for (int rr = 0; rr < 4; rr++)
                if (rr <= e) fma4(a[rr], sW[(r0 + rr) * NDTMAX + (t - rr)], x);
        }
        for (int t = plo + 3; t <= phi; t++) {  // interior: all 4 rows valid
            float4 x = *(const float4*)&sX[(r0 + t) * CJ + col];
            #pragma unroll
            for (int rr = 0; rr < 4; rr++)
                fma4(a[rr], sW[(r0 + rr) * NDTMAX + (t - rr)], x);
        }
        #pragma unroll
        for (int e = 0; e < 3; e++) {           // tail
            int t = phi + 1 + e;
            float4 x = *(const float4*)&sX[(r0 + t) * CJ + col];
            #pragma unroll
            for (int rr = 0; rr < 4; rr++)
                if (rr >= e + 1) fma4(a[rr], sW[(r0 + rr) * NDTMAX + (t - rr)], x);
        }
    } else {
        for (int t = plo; t <= phi + 3; t++) {
            float4 x = *(const float4*)&sX[(r0 + t) * CJ + col];
            #pragma unroll
            for (int rr = 0; rr < 4; rr++) {
                int p = t - rr;
                if (p >= plo && p <= phi)
                    fma4(a[rr], sW[(r0 + rr) * NDTMAX + p], x);
            }
        }
    }
}

__global__ __launch_bounds__(256)
void epilogue_kernel(const float* __restrict__ lt,
                     const float* __restrict__ wq, const float* __restrict__ bq,
                     const float* __restrict__ wk, const float* __restrict__ bk,
                     const float* __restrict__ wv, const float* __restrict__ bv,
                     const float* __restrict__ wmu, const float* __restrict__ bmu,
                     const float* __restrict__ wsig, const float* __restrict__ bsig,
                     const int* __restrict__ k1p, const int* __restrict__ k2p,
                     float* __restrict__ out) {
    extern __shared__ float esm[];
    float* sX  = esm;                 // [XR][CJ]
    float* sW  = esm + XR * CJ;       // [TI][NDTMAX]
    float* sTT = sW + TI * NDTMAX;    // [XR]
    float* sSac = sTT + XR;           // [TI]

    int b = blockIdx.z, i0 = blockIdx.y * TI, c0 = blockIdx.x * CJ;
    int k1 = k1p[0], k2 = k2p[0];
    float invt = 1.0f / (softplusf(lt[0]) + 1e-4f);
    float vwq = wq[0], vbq = bq[0], vwk = wk[0], vbk = bk[0];
    float vwv = wv[0], vbv = bv[0];
    float vwmu = wmu[0], vbmu = bmu[0], vws = wsig[0], vbs = bsig[0];
    int tid = threadIdx.x;
    float* muo = out;
    float* sgo = out + (size_t)NN;
    float* sco = out + 2 * (size_t)NN;

    if (k2 <= K2CAP) {
        int jlo = i0 - k2;
        int nrows = TI + 2 * k2;
        int ndt = 2 * k2 + 1;
        for (int idx = tid; idx < nrows * (CJ / 4); idx += 256) {
            int row = idx >> 4;
            int c4 = (idx & 15) * 4;
            int j = jlo + row;
            float4 v = make_float4(0.f, 0.f, 0.f, 0.f);
            if (j >= 0 && j < WW)
                v = *(const float4*)(g_Xs + (size_t)(b * WW + j) * CC + c0 + c4);
            *(float4*)&sX[row * CJ + c4] = v;
        }
        for (int idx = tid; idx < nrows; idx += 256) {
            int j = jlo + idx;
            float s = 0.f;
            if (j >= 0 && j < WW) {
                #pragma unroll
                for (int q = 0; q < 8; q++)
                    s += g_ttp[(size_t)q * (BB * WW) + (size_t)b * WW + j];
            }
            sTT[idx] = s;
        }
        __syncthreads();

        int lane = tid & 31, wid = tid >> 5;
        for (int r = wid; r < TI; r += 8) {
            int i = i0 + r;
            float qi = fmaf(vwq, sTT[r + k2], vbq);
            float m = -CUDART_INF_F;
            for (int p = lane; p < ndt; p += 32) {
                int dt = p - k2;
                int j = i + dt;
                bool valid = (abs(dt) >= k1) && (j >= 0) && (j < WW);
                float l = valid ? qi * fmaf(vwk, sTT[r + p], vbk) * invt : -CUDART_INF_F;
                sW[r * NDTMAX + p] = l;
                m = fmaxf(m, l);
            }
            #pragma unroll
            for (int o = 16; o; o >>= 1) m = fmaxf(m, __shfl_xor_sync(0xffffffffu, m, o));
            if (m == -CUDART_INF_F) {
                for (int p = lane; p < ndt; p += 32) sW[r * NDTMAX + p] = 0.f;
                __syncwarp();
                if (lane == 0) {
                    sW[r * NDTMAX + k2] = 1.0f / (1.f + 1e-6f);
                    sSac[r] = 1.0f / (1.f + 1e-6f);
                }
            } else {
                float zs = 0.f;
                for (int p = lane; p < ndt; p += 32) {
                    float e = expf(sW[r * NDTMAX + p] - m);
                    sW[r * NDTMAX + p] = e;
                    zs += e;
                }
                #pragma unroll
                for (int o = 16; o; o >>= 1) zs += __shfl_xor_sync(0xffffffffu, zs, o);
                float invz = 1.0f / zs;
                float s2 = 0.f;
                for (int p = lane; p < ndt; p += 32) {
                    float en = sW[r * NDTMAX + p] * invz;
                    sW[r * NDTMAX + p] = en;
                    s2 += en;
                }
                #pragma unroll
                for (int o = 16; o; o >>= 1) s2 += __shfl_xor_sync(0xffffffffu, s2, o);
                float invd = 1.0f / (s2 + 1e-6f);
                for (int p = lane; p < ndt; p += 32) sW[r * NDTMAX + p] *= invd;
                if (lane == 0) sSac[r] = s2 * invd;
            }
        }
        __syncthreads();

        int tx = tid & 15, ty = tid >> 4;
        int col = tx * 4;
        int r0 = ty * 4;
        float4 a[4];
        a[0] = a[1] = a[2] = a[3] = make_float4(0.f, 0.f, 0.f, 0.f);
        if (k1 == 0) {
            band_seg(sX, sW, r0, col, 0, 2 * k2, a);
        } else {
            band_seg(sX, sW, r0, col, 0, k2 - k1, a);
            band_seg(sX, sW, r0, col, k2, k2, a);
            band_seg(sX, sW, r0, col, k2 + k1, 2 * k2, a);
        }
        #pragma unroll
        for (int rr = 0; rr < 4; rr++) {
            int r = r0 + rr;
            int i = i0 + r;
            float sac = sSac[r];
            float4 xo = *(const float4*)&sX[(r + k2) * CJ + col];
            float4 xf, mu, sg;
            xf.x = fmaf(vwv, a[rr].x, vbv * sac) + xo.x;
            xf.y = fmaf(vwv, a[rr].y, vbv * sac) + xo.y;
            xf.z = fmaf(vwv, a[rr].z, vbv * sac) + xo.z;
            xf.w = fmaf(vwv, a[rr].w, vbv * sac) + xo.w;
            mu.x = fminf(fmaxf(fmaf(vwmu, xf.x, vbmu), -20.f), 20.f);
            mu.y = fminf(fmaxf(fmaf(vwmu, xf.y, vbmu), -20.f), 20.f);
            mu.z = fminf(fmaxf(fmaf(vwmu, xf.z, vbmu), -20.f), 20.f);
            mu.w = fminf(fmaxf(fmaf(vwmu, xf.w, vbmu), -20.f), 20.f);
            sg.x = softplusf(fmaf(vws, xf.x, vbs)) + 0.1f;
            sg.y = softplusf(fmaf(vws, xf.y, vbs)) + 0.1f;
            sg.z = softplusf(fmaf(vws, xf.z, vbs)) + 0.1f;
            sg.w = softplusf(fmaf(vws, xf.w, vbs)) + 0.1f;
            size_t o = (size_t)(b * WW + i) * CC + c0 + col;
            *(float4*)(muo + o) = mu;
            *(float4*)(sgo + o) = sg;
            *(float4*)(sco + o) = make_float4(sac, sac, sac, sac);
        }
    } else {
        // correct slow fallback for k2 > K2CAP
        int tx = tid & 15, ty = tid >> 4;
        int col = c0 + tx * 4;
        for (int rr = 0; rr < 4; rr++) {
            int r = ty * 4 + rr;
            int i = i0 + r;
            float tti = 0.f;
            #pragma unroll
            for (int q = 0; q < 8; q++)
                tti += g_ttp[(size_t)q * (BB * WW) + (size_t)b * WW + i];
            float qi = fmaf(vwq, tti, vbq);
            float m = -CUDART_INF_F;
            for (int dt = -k2; dt <= k2; dt++) {
                int j = i + dt;
                if (abs(dt) < k1 || j < 0 || j >= WW) continue;
                float ttj = 0.f;
                #pragma unroll
                for (int q = 0; q < 8; q++)
                    ttj += g_ttp[(size_t)q * (BB * WW) + (size_t)b * WW + j];
                float l = qi * fmaf(vwk, ttj, vbk) * invt;
                m = fmaxf(m, l);
            }
            float4 a = make_float4(0.f, 0.f, 0.f, 0.f);
            float sac = 1.0f / (1.f + 1e-6f);
            if (m == -CUDART_INF_F) {
                float w = sac;
                float4 xi = *(const float4*)(g_Xs + (size_t)(b * WW + i) * CC + col);
                a.x = w * xi.x; a.y = w * xi.y; a.z = w * xi.z; a.w = w * xi.w;
            } else {
                float Z = 0.f;
                for (int dt = -k2; dt <= k2; dt++) {
                    int j = i + dt;
                    if (abs(dt) < k1 || j < 0 || j >= WW) continue;
                    float ttj = 0.f;
                    #pragma unroll
                    for (int q = 0; q < 8; q++)
                        ttj += g_ttp[(size_t)q * (BB * WW) + (size_t)b * WW + j];
                    float l = qi * fmaf(vwk, ttj, vbk) * invt;
                    float e = expf(l - m);
                    Z += e;
                    float4 x = *(const float4*)(g_Xs + (size_t)(b * WW + j) * CC + col);
                    a.x = fmaf(e, x.x, a.x);
                    a.y = fmaf(e, x.y, a.y);
                    a.z = fmaf(e, x.z, a.z);
                    a.w = fmaf(e, x.w, a.w);
                }
                float s = 1.0f / (Z * (1.f + 1e-6f));
                a.x *= s; a.y *= s; a.z *= s; a.w *= s;
            }
            float4 xo = *(const float4*)(g_Xs + (size_t)(b * WW + i) * CC + col);
            float4 xf, mu, sg;
            xf.x = fmaf(vwv, a.x, vbv * sac) + xo.x;
            xf.y = fmaf(vwv, a.y, vbv * sac) + xo.y;
            xf.z = fmaf(vwv, a.z, vbv * sac) + xo.z;
            xf.w = fmaf(vwv, a.w, vbv * sac) + xo.w;
            mu.x = fminf(fmaxf(fmaf(vwmu, xf.x, vbmu), -20.f), 20.f);
            mu.y = fminf(fmaxf(fmaf(vwmu, xf.y, vbmu), -20.f), 20.f);
            mu.z = fminf(fmaxf(fmaf(vwmu, xf.z, vbmu), -20.f), 20.f);
            mu.w = fminf(fmaxf(fmaf(vwmu, xf.w, vbmu), -20.f), 20.f);
            sg.x = softplusf(fmaf(vws, xf.x, vbs)) + 0.1f;
            sg.y = softplusf(fmaf(vws, xf.y, vbs)) + 0.1f;
            sg.z = softplusf(fmaf(vws, xf.z, vbs)) + 0.1f;
            sg.w = softplusf(fmaf(vws, xf.w, vbs)) + 0.1f;
            size_t o = (size_t)(b * WW + i) * CC + c0 + col;
            *(float4*)(muo + o) = mu;
            *(float4*)(sgo + o) = sg;
            *(float4*)(sco + o) = make_float4(sac, sac, sac, sac);
        }
    }
}

// ---------- launch ----------
extern "C" void kernel_launch(void* const* d_in, const int* in_sizes, int n_in,
                              void* d_out, int out_size) {
    const float* X    = (const float*)d_in[0];
    const float* adj  = (const float*)d_in[1];
    const float* lt   = (const float*)d_in[2];
    const float* wq   = (const float*)d_in[3];
    const float* bq   = (const float*)d_in[4];
    const float* wk   = (const float*)d_in[5];
    const float* bk   = (const float*)d_in[6];
    const float* wv   = (const float*)d_in[7];
    const float* bv   = (const float*)d_in[8];
    const float* wmu  = (const float*)d_in[9];
    const float* bmu  = (const float*)d_in[10];
    const float* wsig = (const float*)d_in[11];
    const float* bsig = (const float*)d_in[12];
    const int*   k1p  = (const int*)d_in[13];
    const int*   k2p  = (const int*)d_in[14];
    float* out = (float*)d_out;

    cudaFuncSetAttribute(gemm_kernel,
                         cudaFuncAttributeMaxDynamicSharedMemorySize, SMEM_GEMM);
    cudaFuncSetAttribute(epilogue_kernel,
                         cudaFuncAttributeMaxDynamicSharedMemorySize, SMEM_EPI);

    // order chosen so gemm_kernel is the 4th launch (ncu capture slot)
    presplitX_kernel<<<NN / 4 / 256, 256>>>(X);
    dim3 g1(8, BB);
    deg_partial_kernel<<<g1, 256>>>(adj);
    dim3 gb(16, 16, BB);
    presplitB_kernel<<<gb, dim3(32, 8)>>>(adj);
    dim3 g2(CC / BN, WW / BM, BB);
    gemm_kernel<<<g2, 256, SMEM_GEMM>>>();
    dim3 g5(CC / CJ, WW / TI, BB);
    epilogue_kernel<<<g5, 256, SMEM_EPI>>>(lt, wq, bq, wk, bk, wv, bv, wmu, bmu, wsig, bsig,
                                           k1p, k2p, out);
}

// round 12
// speedup vs baseline: 1.3321x; 1.2645x over previous
#include <cuda_runtime.h>
#include <cuda_bf16.h>
#include <cuda_fp16.h>
#include <math_constants.h>
#include <cstdint>

#define BB 16
#define WW 2048
#define CC 512
#define NN (BB*WW*CC)

// ---------- scratch (no allocations allowed) ----------
__device__ float g_Xs[NN];                 // X_spatial [B,W,C] (64 MB)
__device__ float g_ttp[8*BB*WW];           // partial row sums (8 planes)
__device__ float g_degpart[BB*8*CC];       // partial column sums
__device__ uint32_t g_A16[NN/2];           // X as fp16x2 [b][m][kpair] (32 MB)
__device__ uint2 g_Bp[BB*CC*CC/2];         // norm-adj^T (hi fp16x2, lo fp16x2) [b][n][kpair]

__device__ __forceinline__ float softplusf(float x) {
    return fmaxf(x, 0.f) + log1pf(expf(-fabsf(x)));
}

__device__ __forceinline__ uint32_t h2_pack(float v0, float v1) {
    __half2 h = __floats2half2_rn(v0, v1);
    return *(uint32_t*)&h;
}

// (hi fp16x2, lo fp16x2) split of two floats
__device__ __forceinline__ uint2 h2_split(float v0, float v1) {
    __half h0 = __float2half_rn(v0);
    __half h1 = __float2half_rn(v1);
    float r0 = v0 - __half2float(h0);
    float r1 = v1 - __half2float(h1);
    __half l0 = __float2half_rn(r0);
    __half l1 = __float2half_rn(r1);
    uint2 p;
    p.x = (uint32_t)__half_as_ushort(h0) | ((uint32_t)__half_as_ushort(h1) << 16);
    p.y = (uint32_t)__half_as_ushort(l0) | ((uint32_t)__half_as_ushort(l1) << 16);
    return p;
}

__device__ __forceinline__ void mma_fp16(float* c,
                                         uint32_t a0, uint32_t a1, uint32_t a2, uint32_t a3,
                                         uint32_t b0, uint32_t b1) {
    asm volatile(
        "mma.sync.aligned.m16n8k16.row.col.f32.f16.f16.f32 "
        "{%0,%1,%2,%3},{%4,%5,%6,%7},{%8,%9},{%0,%1,%2,%3};\n"
        : "+f"(c[0]), "+f"(c[1]), "+f"(c[2]), "+f"(c[3])
        : "r"(a0), "r"(a1), "r"(a2), "r"(a3), "r"(b0), "r"(b1));
}

// ---------- K1: X -> fp16x2 plane ----------
__global__ void presplitX_kernel(const float* __restrict__ X) {
    size_t i = ((size_t)blockIdx.x * blockDim.x + threadIdx.x) * 4;
    float4 v = *(const float4*)(X + i);
    uint2 p;
    p.x = h2_pack(v.x, v.y);
    p.y = h2_pack(v.z, v.w);
    *(uint2*)&g_A16[i >> 1] = p;
}

// ---------- K2: partial column sums of relu(adj) ----------
__global__ void deg_partial_kernel(const float* __restrict__ adj) {
    int b = blockIdx.y, chunk = blockIdx.x;
    int i0 = chunk * 64;
    const float* A = adj + (size_t)b * CC * CC;
    for (int j = threadIdx.x; j < CC; j += blockDim.x) {
        float s = 0.f;
        #pragma unroll 8
        for (int i = 0; i < 64; i++)
            s += fmaxf(A[(size_t)(i0 + i) * CC + j], 0.f);
        g_degpart[(b * 8 + chunk) * CC + j] = s;
    }
}

// ---------- K3: B = transpose(relu(adj)) * invdeg -> fp16 hi/lo ----------
__global__ void presplitB_kernel(const float* __restrict__ adj) {
    __shared__ float t[32][33];
    __shared__ float sdeg[32];
    int b = blockIdx.z;
    int i0 = blockIdx.y * 32, j0 = blockIdx.x * 32;
    int tx = threadIdx.x, ty = threadIdx.y;   // (32, 8)
    const float* A = adj + (size_t)b * CC * CC;
    if (ty == 0) {
        float s = 0.f;
        #pragma unroll
        for (int c = 0; c < 8; c++) s += g_degpart[(b * 8 + c) * CC + j0 + tx];
        sdeg[tx] = 1.0f / fmaxf(s, 1e-4f);
    }
    #pragma unroll
    for (int r = 0; r < 4; r++) {
        int il = ty + r * 8;
        t[il][tx] = fmaxf(A[(size_t)(i0 + il) * CC + j0 + tx], 0.f);
    }
    __syncthreads();
    if (tx < 16) {
        #pragma unroll
        for (int r = 0; r < 4; r++) {
            int jl = ty + r * 8;
            int j = j0 + jl;
            float sc = sdeg[jl];
            float v0 = t[2 * tx][jl] * sc;
            float v1 = t[2 * tx + 1][jl] * sc;
            g_Bp[(((size_t)b * CC + j) * CC + i0) / 2 + tx] = h2_split(v0, v1);
        }
    }
}

// ---------- K4: 2xFP16 HMMA GEMM, 3-stage cp.async, fused row sums ----------
#define BM 128
#define BN 128
#define BK 32
#define KP (BK / 2)            // 16 kpairs per chunk
#define SAa 20                 // uint stride for A (conflict-free LDS.32)
#define SAb 20                 // uint2 stride for B (conflict-free LDS.64)
#define NCHUNK (CC / BK)       // 16
#define A_U (128 * SAa)        // uint per A tile
#define B_U2 (128 * SAb)       // uint2 per B tile
#define STAGE_B (A_U * 4 + B_U2 * 8)        // 30720 bytes
#define SMEM_GEMM (3 * STAGE_B)             // 92160 bytes

__global__ void __launch_bounds__(256, 2) gemm_kernel() {
    extern __shared__ unsigned char smraw[];
    int b = blockIdx.z, m0 = blockIdx.y * BM, n0 = blockIdx.x * BN;
    int tid = threadIdx.x;
    int lane = tid & 31, wid = tid >> 5;
    int quad = lane >> 2, tq = lane & 3;
    int wm = wid >> 1, wn = wid & 1;

    uint32_t* As[3];
    uint2* Bs[3];
    #pragma unroll
    for (int s = 0; s < 3; s++) {
        As[s] = (uint32_t*)(smraw + s * STAGE_B);
        Bs[s] = (uint2*)(smraw + s * STAGE_B + A_U * 4);
    }

    const uint32_t* Abase = g_A16 + (size_t)(b * WW + m0) * (CC / 2);
    const uint2* Bbase = g_Bp + ((size_t)b * CC + n0) * (CC / 2);

    float acc[2][8][4];
    #pragma unroll
    for (int am = 0; am < 2; am++)
        #pragma unroll
        for (int an = 0; an < 8; an++)
            #pragma unroll
            for (int q = 0; q < 4; q++) acc[am][an][q] = 0.f;

    #define LOAD_STAGE(c, s) do { \
        int _kp0 = (c) * KP; \
        _Pragma("unroll") \
        for (int it = 0; it < 2; it++) {      /* A: 512 x 16B */ \
            int ch = tid * 2 + it; \
            int row = ch >> 2, c4 = ch & 3; \
            uint32_t dA = (uint32_t)__cvta_generic_to_shared(&As[s][row * SAa + c4 * 4]); \
            const uint32_t* sA = Abase + (size_t)row * (CC / 2) + _kp0 + c4 * 4; \
            asm volatile("cp.async.cg.shared.global [%0], [%1], 16;" \
                :: "r"(dA), "l"((unsigned long long)__cvta_generic_to_global((void*)sA)) : "memory"); \
        } \
        _Pragma("unroll") \
        for (int it = 0; it < 4; it++) {      /* B: 1024 x 16B */ \
            int ch = tid * 4 + it; \
            int row = ch >> 3, c16 = ch & 7; \
            uint32_t dB = (uint32_t)__cvta_generic_to_shared(&Bs[s][row * SAb + c16 * 2]); \
            const uint2* sB = Bbase + (size_t)row * (CC / 2) + _kp0 + c16 * 2; \
            asm volatile("cp.async.cg.shared.global [%0], [%1], 16;" \
                :: "r"(dB), "l"((unsigned long long)__cvta_generic_to_global((void*)sB)) : "memory"); \
        } \
    } while(0)

    LOAD_STAGE(0, 0);
    asm volatile("cp.async.commit_group;" ::: "memory");
    LOAD_STAGE(1, 1);
    asm volatile("cp.async.commit_group;" ::: "memory");

    for (int c = 0; c < NCHUNK; c++) {
        int s = c % 3;
        asm volatile("cp.async.wait_group 1;" ::: "memory");
        __syncthreads();
        // refill the stage freed at iteration c-1 (all threads past the barrier)
        if (c + 2 < NCHUNK) LOAD_STAGE(c + 2, (c + 2) % 3);
        asm volatile("cp.async.commit_group;" ::: "memory");

        #pragma unroll
        for (int ks = 0; ks < 2; ks++) {
            int kb = ks * 8;
            uint32_t ah[2][4];
            #pragma unroll
            for (int am = 0; am < 2; am++) {
                int r0 = wm * 32 + am * 16 + quad;
                ah[am][0] = As[s][r0 * SAa + kb + tq];
                ah[am][1] = As[s][(r0 + 8) * SAa + kb + tq];
                ah[am][2] = As[s][r0 * SAa + kb + 4 + tq];
                ah[am][3] = As[s][(r0 + 8) * SAa + kb + 4 + tq];
            }
            #pragma unroll
            for (int an = 0; an < 8; an++) {
                int c0b = wn * 64 + an * 8 + quad;
                uint2 b0 = Bs[s][c0b * SAb + kb + tq];
                uint2 b1 = Bs[s][c0b * SAb + kb + 4 + tq];
                #pragma unroll
                for (int am = 0; am < 2; am++) {
                    float* cc = acc[am][an];
                    mma_fp16(cc, ah[am][0], ah[am][1], ah[am][2], ah[am][3], b0.x, b1.x);
                    mma_fp16(cc, ah[am][0], ah[am][1], ah[am][2], ah[am][3], b0.y, b1.y);
                }
            }
        }
    }

    // store (invdeg folded into B)
    float* outp = g_Xs + (size_t)b * WW * CC;
    int cbase = n0 + wn * 64;
    #pragma unroll
    for (int am = 0; am < 2; am++) {
        int grow = m0 + wm * 32 + am * 16 + quad;
        #pragma unroll
        for (int an = 0; an < 8; an++) {
            int gc = cbase + an * 8 + tq * 2;
            *(float2*)(outp + (size_t)grow * CC + gc) = make_float2(acc[am][an][0], acc[am][an][1]);
            *(float2*)(outp + (size_t)(grow + 8) * CC + gc) = make_float2(acc[am][an][2], acc[am][an][3]);
        }
    }

    // fused partial row sums (token mean partials); deterministic, no atomics
    float rs00 = 0.f, rs01 = 0.f, rs10 = 0.f, rs11 = 0.f;
    #pragma unroll
    for (int an = 0; an < 8; an++) {
        rs00 += acc[0][an][0] + acc[0][an][1];
        rs01 += acc[0][an][2] + acc[0][an][3];
        rs10 += acc[1][an][0] + acc[1][an][1];
        rs11 += acc[1][an][2] + acc[1][an][3];
    }
    #pragma unroll
    for (int o = 1; o <= 2; o <<= 1) {
        rs00 += __shfl_xor_sync(0xffffffffu, rs00, o);
        rs01 += __shfl_xor_sync(0xffffffffu, rs01, o);
        rs10 += __shfl_xor_sync(0xffffffffu, rs10, o);
        rs11 += __shfl_xor_sync(0xffffffffu, rs11, o);
    }
    if (tq == 0) {
        size_t pl = (size_t)(blockIdx.x * 2 + wn) * (BB * WW) + (size_t)b * WW;
        int r0w = m0 + wm * 32 + quad;
        const float inv = 1.0f / CC;
        g_ttp[pl + r0w]      = rs00 * inv;
        g_ttp[pl + r0w + 8]  = rs01 * inv;
        g_ttp[pl + r0w + 16] = rs10 * inv;
        g_ttp[pl + r0w + 24] = rs11 * inv;
    }
    #undef LOAD_STAGE
}

// ---------- K5: fused band-attention + epilogue ----------
#define TI 64
#define CJ 64
#define K2CAP 40
#define XR (TI + 2 * K2CAP)     // 144
#define NDTMAX (2 * K2CAP + 1)  // 81
#define SMEM_EPI ((XR * CJ + TI * NDTMAX + XR + TI) * 4)

__device__ __forceinline__ void fma4(float4& a, float w, const float4& x) {
    a.x = fmaf(w, x.x, a.x);
    a.y = fmaf(w, x.y, a.y);
    a.z = fmaf(w, x.z, a.z);
    a.w = fmaf(w, x.w, a.w);
}

__device__ __forceinline__ void band_seg(const float* __restrict__ sX,
                                         const float* __restrict__ sW,
                                         int r0, int col, int plo, int phi,
                                         float4* a) {
    if (phi < plo) return;
    if (phi - plo >= 3) {
        #pragma unroll
        for (int e = 0; e < 3; e++) {
            int t = plo + e;
            float4 x = *(const float4*)&sX[(r0 + t) * CJ + col];
            #pragma unroll
            for (int rr = 0; rr < 4; rr++)
                if (rr <= e) fma4(a[rr], sW[(r0 + rr) * NDTMAX + (t - rr)], x);
        }
        for (int t = plo + 3; t <= phi; t++) {
            float4 x = *(const float4*)&sX[(r0 + t) * CJ + col];
            #pragma unroll
            for (int rr = 0; rr < 4; rr++)
                fma4(a[rr], sW[(r0 + rr) * NDTMAX + (t - rr)], x);
        }
        #pragma unroll
        for (int e = 0; e < 3; e++) {
            int t = phi + 1 + e;
            float4 x = *(const float4*)&sX[(r0 + t) * CJ + col];
            #pragma unroll
            for (int rr = 0; rr < 4; rr++)
                if (rr >= e + 1) fma4(a[rr], sW[(r0 + rr) * NDTMAX + (t - rr)], x);
        }
    } else {
        for (int t = plo; t <= phi + 3; t++) {
            float4 x = *(const float4*)&sX[(r0 + t) * CJ + col];
            #pragma unroll
            for (int rr = 0; rr < 4; rr++) {
                int p = t - rr;
                if (p >= plo && p <= phi)
                    fma4(a[rr], sW[(r0 + rr) * NDTMAX + p], x);
            }
        }
    }
}

__global__ __launch_bounds__(256)
void epilogue_kernel(const float* __restrict__ lt,
                     const float* __restrict__ wq, const float* __restrict__ bq,
                     const float* __restrict__ wk, const float* __restrict__ bk,
                     const float* __restrict__ wv, const float* __restrict__ bv,
                     const float* __restrict__ wmu, const float* __restrict__ bmu,
                     const float* __restrict__ wsig, const float* __restrict__ bsig,
                     const int* __restrict__ k1p, const int* __restrict__ k2p,
                     float* __restrict__ out) {
    extern __shared__ float esm[];
    float* sX  = esm;
    float* sW  = esm + XR * CJ;
    float* sTT = sW + TI * NDTMAX;
    float* sSac = sTT + XR;

    int b = blockIdx.z, i0 = blockIdx.y * TI, c0 = blockIdx.x * CJ;
    int k1 = k1p[0], k2 = k2p[0];
    float invt = 1.0f / (softplusf(lt[0]) + 1e-4f);
    float vwq = wq[0], vbq = bq[0], vwk = wk[0], vbk = bk[0];
    float vwv = wv[0], vbv = bv[0];
    float vwmu = wmu[0], vbmu = bmu[0], vws = wsig[0], vbs = bsig[0];
    int tid = threadIdx.x;
    float* muo = out;
    float* sgo = out + (size_t)NN;
    float* sco = out + 2 * (size_t)NN;

    if (k2 <= K2CAP) {
        int jlo = i0 - k2;
        int nrows = TI + 2 * k2;
        int ndt = 2 * k2 + 1;
        for (int idx = tid; idx < nrows * (CJ / 4); idx += 256) {
            int row = idx >> 4;
            int c4 = (idx & 15) * 4;
            int j = jlo + row;
            float4 v = make_float4(0.f, 0.f, 0.f, 0.f);
            if (j >= 0 && j < WW)
                v = *(const float4*)(g_Xs + (size_t)(b * WW + j) * CC + c0 + c4);
            *(float4*)&sX[row * CJ + c4] = v;
        }
        for (int idx = tid; idx < nrows; idx += 256) {
            int j = jlo + idx;
            float s = 0.f;
            if (j >= 0 && j < WW) {
                #pragma unroll
                for (int q = 0; q < 8; q++)
                    s += g_ttp[(size_t)q * (BB * WW) + (size_t)b * WW + j];
            }
            sTT[idx] = s;
        }
        __syncthreads();

        int lane = tid & 31, wid = tid >> 5;
        for (int r = wid; r < TI; r += 8) {
            int i = i0 + r;
            float qi = fmaf(vwq, sTT[r + k2], vbq);
            float m = -CUDART_INF_F;
            for (int p = lane; p < ndt; p += 32) {
                int dt = p - k2;
                int j = i + dt;
                bool valid = (abs(dt) >= k1) && (j >= 0) && (j < WW);
                float l = valid ? qi * fmaf(vwk, sTT[r + p], vbk) * invt : -CUDART_INF_F;
                sW[r * NDTMAX + p] = l;
                m = fmaxf(m, l);
            }
            #pragma unroll
            for (int o = 16; o; o >>= 1) m = fmaxf(m, __shfl_xor_sync(0xffffffffu, m, o));
            if (m == -CUDART_INF_F) {
                for (int p = lane; p < ndt; p += 32) sW[r * NDTMAX + p] = 0.f;
                __syncwarp();
                if (lane == 0) {
                    sW[r * NDTMAX + k2] = 1.0f / (1.f + 1e-6f);
                    sSac[r] = 1.0f / (1.f + 1e-6f);
                }
            } else {
                float zs = 0.f;
                for (int p = lane; p < ndt; p += 32) {
                    float e = expf(sW[r * NDTMAX + p] - m);
                    sW[r * NDTMAX + p] = e;
                    zs += e;
                }
                #pragma unroll
                for (int o = 16; o; o >>= 1) zs += __shfl_xor_sync(0xffffffffu, zs, o);
                float invz = 1.0f / zs;
                float s2 = 0.f;
                for (int p = lane; p < ndt; p += 32) {
                    float en = sW[r * NDTMAX + p] * invz;
                    sW[r * NDTMAX + p] = en;
                    s2 += en;
                }
                #pragma unroll
                for (int o = 16; o; o >>= 1) s2 += __shfl_xor_sync(0xffffffffu, s2, o);
                float invd = 1.0f / (s2 + 1e-6f);
                for (int p = lane; p < ndt; p += 32) sW[r * NDTMAX + p] *= invd;
                if (lane == 0) sSac[r] = s2 * invd;
            }
        }
        __syncthreads();

        int tx = tid & 15, ty = tid >> 4;
        int col = tx * 4;
        int r0 = ty * 4;
        float4 a[4];
        a[0] = a[1] = a[2] = a[3] = make_float4(0.f, 0.f, 0.f, 0.f);
        if (k1 == 0) {
            band_seg(sX, sW, r0, col, 0, 2 * k2, a);
        } else {
            band_seg(sX, sW, r0, col, 0, k2 - k1, a);
            band_seg(sX, sW, r0, col, k2, k2, a);
            band_seg(sX, sW, r0, col, k2 + k1, 2 * k2, a);
        }
        #pragma unroll
        for (int rr = 0; rr < 4; rr++) {
            int r = r0 + rr;
            int i = i0 + r;
            float sac = sSac[r];
            float4 xo = *(const float4*)&sX[(r + k2) * CJ + col];
            float4 xf, mu, sg;
            xf.x = fmaf(vwv, a[rr].x, vbv * sac) + xo.x;
            xf.y = fmaf(vwv, a[rr].y, vbv * sac) + xo.y;
            xf.z = fmaf(vwv, a[rr].z, vbv * sac) + xo.z;
            xf.w = fmaf(vwv, a[rr].w, vbv * sac) + xo.w;
            mu.x = fminf(fmaxf(fmaf(vwmu, xf.x, vbmu), -20.f), 20.f);
            mu.y = fminf(fmaxf(fmaf(vwmu, xf.y, vbmu), -20.f), 20.f);
            mu.z = fminf(fmaxf(fmaf(vwmu, xf.z, vbmu), -20.f), 20.f);
            mu.w = fminf(fmaxf(fmaf(vwmu, xf.w, vbmu), -20.f), 20.f);
            sg.x = softplusf(fmaf(vws, xf.x, vbs)) + 0.1f;
            sg.y = softplusf(fmaf(vws, xf.y, vbs)) + 0.1f;
            sg.z = softplusf(fmaf(vws, xf.z, vbs)) + 0.1f;
            sg.w = softplusf(fmaf(vws, xf.w, vbs)) + 0.1f;
            size_t o = (size_t)(b * WW + i) * CC + c0 + col;
            *(float4*)(muo + o) = mu;
            *(float4*)(sgo + o) = sg;
            *(float4*)(sco + o) = make_float4(sac, sac, sac, sac);
        }
    } else {
        // correct slow fallback for k2 > K2CAP
        int tx = tid & 15, ty = tid >> 4;
        int col = c0 + tx * 4;
        for (int rr = 0; rr < 4; rr++) {
            int r = ty * 4 + rr;
            int i = i0 + r;
            float tti = 0.f;
            #pragma unroll
            for (int q = 0; q < 8; q++)
                tti += g_ttp[(size_t)q * (BB * WW) + (size_t)b * WW + i];
            float qi = fmaf(vwq, tti, vbq);
            float m = -CUDART_INF_F;
            for (int dt = -k2; dt <= k2; dt++) {
                int j = i + dt;
                if (abs(dt) < k1 || j < 0 || j >= WW) continue;
                float ttj = 0.f;
                #pragma unroll
                for (int q = 0; q < 8; q++)
                    ttj += g_ttp[(size_t)q * (BB * WW) + (size_t)b * WW + j];
                float l = qi * fmaf(vwk, ttj, vbk) * invt;
                m = fmaxf(m, l);
            }
            float4 a = make_float4(0.f, 0.f, 0.f, 0.f);
            float sac = 1.0f / (1.f + 1e-6f);
            if (m == -CUDART_INF_F) {
                float w = sac;
                float4 xi = *(const float4*)(g_Xs + (size_t)(b * WW + i) * CC + col);
                a.x = w * xi.x; a.y = w * xi.y; a.z = w * xi.z; a.w = w * xi.w;
            } else {
                float Z = 0.f;
                for (int dt = -k2; dt <= k2; dt++) {
                    int j = i + dt;
                    if (abs(dt) < k1 || j < 0 || j >= WW) continue;
                    float ttj = 0.f;
                    #pragma unroll
                    for (int q = 0; q < 8; q++)
                        ttj += g_ttp[(size_t)q * (BB * WW) + (size_t)b * WW + j];
                    float l = qi * fmaf(vwk, ttj, vbk) * invt;
                    float e = expf(l - m);
                    Z += e;
                    float4 x = *(const float4*)(g_Xs + (size_t)(b * WW + j) * CC + col);
                    a.x = fmaf(e, x.x, a.x);
                    a.y = fmaf(e, x.y, a.y);
                    a.z = fmaf(e, x.z, a.z);
                    a.w = fmaf(e, x.w, a.w);
                }
                float s = 1.0f / (Z * (1.f + 1e-6f));
                a.x *= s; a.y *= s; a.z *= s; a.w *= s;
            }
            float4 xo = *(const float4*)(g_Xs + (size_t)(b * WW + i) * CC + col);
            float4 xf, mu, sg;
            xf.x = fmaf(vwv, a.x, vbv * sac) + xo.x;
            xf.y = fmaf(vwv, a.y, vbv * sac) + xo.y;
            xf.z = fmaf(vwv, a.z, vbv * sac) + xo.z;
            xf.w = fmaf(vwv, a.w, vbv * sac) + xo.w;
            mu.x = fminf(fmaxf(fmaf(vwmu, xf.x, vbmu), -20.f), 20.f);
            mu.y = fminf(fmaxf(fmaf(vwmu, xf.y, vbmu), -20.f), 20.f);
            mu.z = fminf(fmaxf(fmaf(vwmu, xf.z, vbmu), -20.f), 20.f);
            mu.w = fminf(fmaxf(fmaf(vwmu, xf.w, vbmu), -20.f), 20.f);
            sg.x = softplusf(fmaf(vws, xf.x, vbs)) + 0.1f;
            sg.y = softplusf(fmaf(vws, xf.y, vbs)) + 0.1f;
            sg.z = softplusf(fmaf(vws, xf.z, vbs)) + 0.1f;
            sg.w = softplusf(fmaf(vws, xf.w, vbs)) + 0.1f;
            size_t o = (size_t)(b * WW + i) * CC + c0 + col;
            *(float4*)(muo + o) = mu;
            *(float4*)(sgo + o) = sg;
            *(float4*)(sco + o) = make_float4(sac, sac, sac, sac);
        }
    }
}

// ---------- launch ----------
extern "C" void kernel_launch(void* const* d_in, const int* in_sizes, int n_in,
                              void* d_out, int out_size) {
    const float* X    = (const float*)d_in[0];
    const float* adj  = (const float*)d_in[1];
    const float* lt   = (const float*)d_in[2];
    const float* wq   = (const float*)d_in[3];
    const float* bq   = (const float*)d_in[4];
    const float* wk   = (const float*)d_in[5];
    const float* bk   = (const float*)d_in[6];
    const float* wv   = (const float*)d_in[7];
    const float* bv   = (const float*)d_in[8];
    const float* wmu  = (const float*)d_in[9];
    const float* bmu  = (const float*)d_in[10];
    const float* wsig = (const float*)d_in[11];
    const float* bsig = (const float*)d_in[12];
    const int*   k1p  = (const int*)d_in[13];
    const int*   k2p  = (const int*)d_in[14];
    float* out = (float*)d_out;

    cudaFuncSetAttribute(gemm_kernel,
                         cudaFuncAttributeMaxDynamicSharedMemorySize, SMEM_GEMM);
    cudaFuncSetAttribute(epilogue_kernel,
                         cudaFuncAttributeMaxDynamicSharedMemorySize, SMEM_EPI);

    // order chosen so gemm_kernel is the 4th launch (ncu capture slot)
    presplitX_kernel<<<NN / 4 / 256, 256>>>(X);
    dim3 g1(8, BB);
    deg_partial_kernel<<<g1, 256>>>(adj);
    dim3 gb(16, 16, BB);
    presplitB_kernel<<<gb, dim3(32, 8)>>>(adj);
    dim3 g2(CC / BN, WW / BM, BB);
    gemm_kernel<<<g2, 256, SMEM_GEMM>>>();
    dim3 g5(CC / CJ, WW / TI, BB);
    epilogue_kernel<<<g5, 256, SMEM_EPI>>>(lt, wq, bq, wk, bk, wv, bv, wmu, bmu, wsig, bsig,
                                           k1p, k2p, out);
}

// round 14
// speedup vs baseline: 1.6792x; 1.2606x over previous
#include <cuda_runtime.h>
#include <cuda_fp16.h>
#include <math_constants.h>
#include <cstdint>

#define BB 16
#define WW 2048
#define CC 512
#define NN (BB*WW*CC)

// ---------- scratch (no allocations allowed) ----------
__device__ float g_Xs[NN];                 // X_spatial [B,W,C] (64 MB)
__device__ float g_ttp[8*BB*WW];           // partial row sums (8 planes)
__device__ float g_degpart[BB*8*CC];       // partial column sums
__device__ uint32_t g_A16[NN/2];           // X fp16x2, k-pair-permuted (32 MB)
__device__ uint32_t g_B16[BB*CC*CC/2];     // norm-adj^T fp16x2, permuted (8 MB)

__device__ __forceinline__ float softplusf(float x) {
    return fmaxf(x, 0.f) + log1pf(expf(-fabsf(x)));
}

__device__ __forceinline__ uint32_t h2_pack(float v0, float v1) {
    __half2 h = __floats2half2_rn(v0, v1);
    return *(uint32_t*)&h;
}

// k-pair permutation within 8-groups: [0,4,1,5,2,6,3,7] so that
// LDS.64 at pos 2*tq yields kpairs (tq, tq+4) = both fragment quarters.
__device__ __forceinline__ uint32_t kperm(uint32_t kp) {
    uint32_t loc = kp & 7u;
    uint32_t pos = (loc < 4u) ? (2u * loc) : (2u * (loc - 4u) + 1u);
    return (kp & ~7u) | pos;
}

__device__ __forceinline__ void mma_fp16(float* c,
                                         uint32_t a0, uint32_t a1, uint32_t a2, uint32_t a3,
                                         uint32_t b0, uint32_t b1) {
    asm volatile(
        "mma.sync.aligned.m16n8k16.row.col.f32.f16.f16.f32 "
        "{%0,%1,%2,%3},{%4,%5,%6,%7},{%8,%9},{%0,%1,%2,%3};\n"
        : "+f"(c[0]), "+f"(c[1]), "+f"(c[2]), "+f"(c[3])
        : "r"(a0), "r"(a1), "r"(a2), "r"(a3), "r"(b0), "r"(b1));
}

// ---------- K1: fused presplitX + deg partial sums ----------
#define NXBLK (NN / 1024)    // 16384 blocks for the X part

__global__ void prep_kernel(const float* __restrict__ X, const float* __restrict__ adj) {
    if (blockIdx.x < NXBLK) {
        size_t i = ((size_t)blockIdx.x * 256 + threadIdx.x) * 4;
        float4 v = *(const float4*)(X + i);
        uint32_t kp = (uint32_t)(i >> 1);       // even kpair index
        uint32_t kp1 = kp + 1;
        size_t grp_base = (i >> 1) & ~7ULL;     // 8-kpair group base
        g_A16[grp_base + (kperm(kp) & 7u)]  = h2_pack(v.x, v.y);
        g_A16[grp_base + (kperm(kp1) & 7u)] = h2_pack(v.z, v.w);
    } else {
        int idx = blockIdx.x - NXBLK;     // 0..127
        int b = idx >> 3, chunk = idx & 7;
        int i0 = chunk * 64;
        const float* A = adj + (size_t)b * CC * CC;
        for (int j = threadIdx.x; j < CC; j += 256) {
            float s = 0.f;
            #pragma unroll 8
            for (int i = 0; i < 64; i++)
                s += fmaxf(A[(size_t)(i0 + i) * CC + j], 0.f);
            g_degpart[(b * 8 + chunk) * CC + j] = s;
        }
    }
}

// ---------- K2: B = transpose(relu(adj)) * invdeg -> fp16 plane (permuted) ----------
__global__ void presplitB_kernel(const float* __restrict__ adj) {
    __shared__ float t[32][33];
    __shared__ float sdeg[32];
    int b = blockIdx.z;
    int i0 = blockIdx.y * 32, j0 = blockIdx.x * 32;
    int tx = threadIdx.x, ty = threadIdx.y;   // (32, 8)
    const float* A = adj + (size_t)b * CC * CC;
    if (ty == 0) {
        float s = 0.f;
        #pragma unroll
        for (int c = 0; c < 8; c++) s += g_degpart[(b * 8 + c) * CC + j0 + tx];
        sdeg[tx] = 1.0f / fmaxf(s, 1e-4f);
    }
    #pragma unroll
    for (int r = 0; r < 4; r++) {
        int il = ty + r * 8;
        t[il][tx] = fmaxf(A[(size_t)(i0 + il) * CC + j0 + tx], 0.f);
    }
    __syncthreads();
    if (tx < 16) {
        #pragma unroll
        for (int r = 0; r < 4; r++) {
            int jl = ty + r * 8;
            int j = j0 + jl;
            float sc = sdeg[jl];
            float v0 = t[2 * tx][jl] * sc;
            float v1 = t[2 * tx + 1][jl] * sc;
            uint32_t kp = (uint32_t)(i0 / 2 + tx);    // kpair index within row
            size_t rowbase = ((size_t)b * CC + j) * (CC / 2);
            g_B16[rowbase + (kp & ~7u) + (kperm(kp) & 7u)] = h2_pack(v0, v1);
        }
    }
}

// ---------- K3: fp16 HMMA GEMM, 3-stage cp.async, LDS.64 fragments ----------
#define BM 128
#define BN 128
#define BK 32
#define KPC 16                 // kpairs per chunk
#define ST 24                  // uint row stride (16 data + 8 pad): bank-perfect LDS.64
#define NCHUNK (CC / BK)       // 16
#define TILE_U (128 * ST)      // uints per tile
#define STAGE_B (TILE_U * 4 * 2)           // A + B, bytes = 24576
#define SMEM_GEMM (3 * STAGE_B)            // 73728

__global__ void __launch_bounds__(256, 2) gemm_kernel() {
    extern __shared__ unsigned char smraw[];
    int b = blockIdx.z, m0 = blockIdx.y * BM, n0 = blockIdx.x * BN;
    int tid = threadIdx.x;
    int lane = tid & 31, wid = tid >> 5;
    int quad = lane >> 2, tq = lane & 3;
    int wm = wid >> 1, wn = wid & 1;

    uint32_t* As[3];
    uint32_t* Bs[3];
    #pragma unroll
    for (int s = 0; s < 3; s++) {
        As[s] = (uint32_t*)(smraw + s * STAGE_B);
        Bs[s] = (uint32_t*)(smraw + s * STAGE_B + TILE_U * 4);
    }

    const uint32_t* Abase = g_A16 + (size_t)(b * WW + m0) * (CC / 2);
    const uint32_t* Bbase = g_B16 + ((size_t)b * CC + n0) * (CC / 2);

    float acc[2][8][4];
    #pragma unroll
    for (int am = 0; am < 2; am++)
        #pragma unroll
        for (int an = 0; an < 8; an++)
            #pragma unroll
            for (int q = 0; q < 4; q++) acc[am][an][q] = 0.f;

    #define LOAD_STAGE(c, s) do { \
        int _kp0 = (c) * KPC; \
        _Pragma("unroll") \
        for (int it = 0; it < 2; it++) { \
            int ch = tid * 2 + it; \
            int row = ch >> 2, c16 = ch & 3; \
            uint32_t dA = (uint32_t)__cvta_generic_to_shared(&As[s][row * ST + c16 * 4]); \
            const uint32_t* sA = Abase + (size_t)row * (CC / 2) + _kp0 + c16 * 4; \
            asm volatile("cp.async.cg.shared.global [%0], [%1], 16;" \
                :: "r"(dA), "l"((unsigned long long)__cvta_generic_to_global((void*)sA)) : "memory"); \
            uint32_t dB = (uint32_t)__cvta_generic_to_shared(&Bs[s][row * ST + c16 * 4]); \
            const uint32_t* sB = Bbase + (size_t)row * (CC / 2) + _kp0 + c16 * 4; \
            asm volatile("cp.async.cg.shared.global [%0], [%1], 16;" \
                :: "r"(dB), "l"((unsigned long long)__cvta_generic_to_global((void*)sB)) : "memory"); \
        } \
    } while(0)

    LOAD_STAGE(0, 0);
    asm volatile("cp.async.commit_group;" ::: "memory");
    LOAD_STAGE(1, 1);
    asm volatile("cp.async.commit_group;" ::: "memory");

    for (int c = 0; c < NCHUNK; c++) {
        int s = c % 3;
        asm volatile("cp.async.wait_group 1;" ::: "memory");
        __syncthreads();
        if (c + 2 < NCHUNK) LOAD_STAGE(c + 2, (c + 2) % 3);
        asm volatile("cp.async.commit_group;" ::: "memory");

        #pragma unroll
        for (int ks = 0; ks < 2; ks++) {
            int kb = ks * 8;
            // A fragments: LDS.64 gives (kq=tq, kq=tq+4) per row via permuted layout
            uint2 aA[2], aB[2];
            #pragma unroll
            for (int am = 0; am < 2; am++) {
                int r0 = wm * 32 + am * 16 + quad;
                aA[am] = *(uint2*)&As[s][r0 * ST + kb + 2 * tq];
                aB[am] = *(uint2*)&As[s][(r0 + 8) * ST + kb + 2 * tq];
            }
            #pragma unroll
            for (int an = 0; an < 8; an++) {
                int c0b = wn * 64 + an * 8 + quad;
                uint2 bb = *(uint2*)&Bs[s][c0b * ST + kb + 2 * tq];
                #pragma unroll
                for (int am = 0; am < 2; am++) {
                    mma_fp16(acc[am][an], aA[am].x, aB[am].x, aA[am].y, aB[am].y,
                             bb.x, bb.y);
                }
            }
        }
    }

    // store (invdeg folded into B)
    float* outp = g_Xs + (size_t)b * WW * CC;
    int cbase = n0 + wn * 64;
    #pragma unroll
    for (int am = 0; am < 2; am++) {
        int grow = m0 + wm * 32 + am * 16 + quad;
        #pragma unroll
        for (int an = 0; an < 8; an++) {
            int gc = cbase + an * 8 + tq * 2;
            *(float2*)(outp + (size_t)grow * CC + gc) = make_float2(acc[am][an][0], acc[am][an][1]);
            *(float2*)(outp + (size_t)(grow + 8) * CC + gc) = make_float2(acc[am][an][2], acc[am][an][3]);
        }
    }

    // fused partial row sums; deterministic, no atomics
    float rs00 = 0.f, rs01 = 0.f, rs10 = 0.f, rs11 = 0.f;
    #pragma unroll
    for (int an = 0; an < 8; an++) {
        rs00 += acc[0][an][0] + acc[0][an][1];
        rs01 += acc[0][an][2] + acc[0][an][3];
        rs10 += acc[1][an][0] + acc[1][an][1];
        rs11 += acc[1][an][2] + acc[1][an][3];
    }
    #pragma unroll
    for (int o = 1; o <= 2; o <<= 1) {
        rs00 += __shfl_xor_sync(0xffffffffu, rs00, o);
        rs01 += __shfl_xor_sync(0xffffffffu, rs01, o);
        rs10 += __shfl_xor_sync(0xffffffffu, rs10, o);
        rs11 += __shfl_xor_sync(0xffffffffu, rs11, o);
    }
    if (tq == 0) {
        size_t pl = (size_t)(blockIdx.x * 2 + wn) * (BB * WW) + (size_t)b * WW;
        int r0w = m0 + wm * 32 + quad;
        const float inv = 1.0f / CC;
        g_ttp[pl + r0w]      = rs00 * inv;
        g_ttp[pl + r0w + 8]  = rs01 * inv;
        g_ttp[pl + r0w + 16] = rs10 * inv;
        g_ttp[pl + r0w + 24] = rs11 * inv;
    }
    #undef LOAD_STAGE
}

// ---------- K4: fused band-attention + epilogue (diagonal weights) ----------
#define TI 64
#define CJ 64
#define K2CAP 32
#define XR (TI + 2 * K2CAP)     // 128
#define NDTMAX (2 * K2CAP + 1)  // 65
#define SDW 68                  // sD row stride (floats): float4-aligned
#define SDROWS XR               // 128 diagonal rows
#define SMEM_EPI ((XR * CJ + SDROWS * SDW + XR + TI) * 4)

__global__ __launch_bounds__(256)
void epilogue_kernel(const float* __restrict__ lt,
                     const float* __restrict__ wq, const float* __restrict__ bq,
                     const float* __restrict__ wk, const float* __restrict__ bk,
                     const float* __restrict__ wv, const float* __restrict__ bv,
                     const float* __restrict__ wmu, const float* __restrict__ bmu,
                     const float* __restrict__ wsig, const float* __restrict__ bsig,
                     const int* __restrict__ k1p, const int* __restrict__ k2p,
                     float* __restrict__ out) {
    extern __shared__ float esm[];
    float* sX  = esm;                      // [XR][CJ]
    float* sD  = esm + XR * CJ;            // [SDROWS][SDW]  diag: sD[r+p][r]=w[r][p]
    float* sTT = sD + SDROWS * SDW;        // [XR]
    float* sSac = sTT + XR;                // [TI]

    int b = blockIdx.z, i0 = blockIdx.y * TI, c0 = blockIdx.x * CJ;
    int k1 = k1p[0], k2 = k2p[0];
    float invt = 1.0f / (softplusf(lt[0]) + 1e-4f);
    float vwq = wq[0], vbq = bq[0], vwk = wk[0], vbk = bk[0];
    float vwv = wv[0], vbv = bv[0];
    float vwmu = wmu[0], vbmu = bmu[0], vws = wsig[0], vbs = bsig[0];
    int tid = threadIdx.x;
    float* muo = out;
    float* sgo = out + (size_t)NN;
    float* sco = out + 2 * (size_t)NN;

    if (k2 <= K2CAP) {
        int jlo = i0 - k2;
        int nrows = TI + 2 * k2;
        int ndt = 2 * k2 + 1;
        // zero sD
        for (int idx = tid; idx < SDROWS * SDW / 4; idx += 256)
            *(float4*)&sD[idx * 4] = make_float4(0.f, 0.f, 0.f, 0.f);
        // load X window + token window
        for (int idx = tid; idx < nrows * (CJ / 4); idx += 256) {
            int row = idx >> 4;
            int c4 = (idx & 15) * 4;
            int j = jlo + row;
            float4 v = make_float4(0.f, 0.f, 0.f, 0.f);
            if (j >= 0 && j < WW)
                v = *(const float4*)(g_Xs + (size_t)(b * WW + j) * CC + c0 + c4);
            *(float4*)&sX[row * CJ + c4] = v;
        }
        for (int idx = tid; idx < nrows; idx += 256) {
            int j = jlo + idx;
            float s = 0.f;
            if (j >= 0 && j < WW) {
                #pragma unroll
                for (int q = 0; q < 8; q++)
                    s += g_ttp[(size_t)q * (BB * WW) + (size_t)b * WW + j];
            }
            sTT[idx] = s;
        }
        __syncthreads();

        int lane = tid & 31, wid = tid >> 5;
        for (int r = wid; r < TI; r += 8) {
            int i = i0 + r;
            float qi = fmaf(vwq, sTT[r + k2], vbq);
            float m = -CUDART_INF_F;
            float lv[3];
            #pragma unroll
            for (int q = 0; q < 3; q++) {
                int p = lane + q * 32;
                lv[q] = -CUDART_INF_F;
                if (p < ndt) {
                    int dt = p - k2;
                    int j = i + dt;
                    bool valid = (abs(dt) >= k1) && (j >= 0) && (j < WW);
                    if (valid) lv[q] = qi * fmaf(vwk, sTT[r + p], vbk) * invt;
                    m = fmaxf(m, lv[q]);
                }
            }
            #pragma unroll
            for (int o = 16; o; o >>= 1) m = fmaxf(m, __shfl_xor_sync(0xffffffffu, m, o));
            if (m == -CUDART_INF_F) {
                if (lane == 0) {
                    sD[(r + k2) * SDW + r] = 1.0f / (1.f + 1e-6f);
                    sSac[r] = 1.0f / (1.f + 1e-6f);
                }
            } else {
                float e[3]; float zs = 0.f;
                #pragma unroll
                for (int q = 0; q < 3; q++) {
                    int p = lane + q * 32;
                    e[q] = (p < ndt) ? expf(lv[q] - m) : 0.f;   // exp(-inf)=0
                    zs += e[q];
                }
                #pragma unroll
                for (int o = 16; o; o >>= 1) zs += __shfl_xor_sync(0xffffffffu, zs, o);
                float invz = 1.0f / zs;
                float s2 = 0.f;
                #pragma unroll
                for (int q = 0; q < 3; q++) { e[q] *= invz; s2 += e[q]; }
                #pragma unroll
                for (int o = 16; o; o >>= 1) s2 += __shfl_xor_sync(0xffffffffu, s2, o);
                float invd = 1.0f / (s2 + 1e-6f);
                #pragma unroll
                for (int q = 0; q < 3; q++) {
                    int p = lane + q * 32;
                    if (p < ndt) sD[(r + p) * SDW + r] = e[q] * invd;
                }
                if (lane == 0) sSac[r] = s2 * invd;
            }
        }
        __syncthreads();

        // banded weighted sum via diagonal float4 weight reads (zeros mask edges)
        int tx = tid & 15, ty = tid >> 4;
        int col = tx * 4;
        int r0 = ty * 4;
        float4 a0 = make_float4(0.f,0.f,0.f,0.f), a1 = a0, a2 = a0, a3 = a0;
        #define BAND_RANGE(PLO, PHI) \
            for (int t = (PLO); t <= (PHI) + 3; t++) { \
                float4 x = *(const float4*)&sX[(r0 + t) * CJ + col]; \
                float4 w = *(const float4*)&sD[(r0 + t) * SDW + r0]; \
                a0.x = fmaf(w.x, x.x, a0.x); a0.y = fmaf(w.x, x.y, a0.y); \
                a0.z = fmaf(w.x, x.z, a0.z); a0.w = fmaf(w.x, x.w, a0.w); \
                a1.x = fmaf(w.y, x.x, a1.x); a1.y = fmaf(w.y, x.y, a1.y); \
                a1.z = fmaf(w.y, x.z, a1.z); a1.w = fmaf(w.y, x.w, a1.w); \
                a2.x = fmaf(w.z, x.x, a2.x); a2.y = fmaf(w.z, x.y, a2.y); \
                a2.z = fmaf(w.z, x.z, a2.z); a2.w = fmaf(w.z, x.w, a2.w); \
                a3.x = fmaf(w.w, x.x, a3.x); a3.y = fmaf(w.w, x.y, a3.y); \
                a3.z = fmaf(w.w, x.z, a3.z); a3.w = fmaf(w.w, x.w, a3.w); \
            }
        if (k1 >= 4) {
            BAND_RANGE(0, k2 - k1);
            BAND_RANGE(k2, k2);            // identity-fallback center
            BAND_RANGE(k2 + k1, 2 * k2);
        } else {
            BAND_RANGE(0, 2 * k2);
        }
        #undef BAND_RANGE

        float4 av[4] = { a0, a1, a2, a3 };
        #pragma unroll
        for (int rr = 0; rr < 4; rr++) {
            int r = r0 + rr;
            int i = i0 + r;
            float sac = sSac[r];
            float4 xo = *(const float4*)&sX[(r + k2) * CJ + col];
            float4 xf, mu, sg;
            xf.x = fmaf(vwv, av[rr].x, vbv * sac) + xo.x;
            xf.y = fmaf(vwv, av[rr].y, vbv * sac) + xo.y;
            xf.z = fmaf(vwv, av[rr].z, vbv * sac) + xo.z;
            xf.w = fmaf(vwv, av[rr].w, vbv * sac) + xo.w;
            mu.x = fminf(fmaxf(fmaf(vwmu, xf.x, vbmu), -20.f), 20.f);
            mu.y = fminf(fmaxf(fmaf(vwmu, xf.y, vbmu), -20.f), 20.f);
            mu.z = fminf(fmaxf(fmaf(vwmu, xf.z, vbmu), -20.f), 20.f);
            mu.w = fminf(fmaxf(fmaf(vwmu, xf.w, vbmu), -20.f), 20.f);
            sg.x = softplusf(fmaf(vws, xf.x, vbs)) + 0.1f;
            sg.y = softplusf(fmaf(vws, xf.y, vbs)) + 0.1f;
            sg.z = softplusf(fmaf(vws, xf.z, vbs)) + 0.1f;
            sg.w = softplusf(fmaf(vws, xf.w, vbs)) + 0.1f;
            size_t o = (size_t)(b * WW + i) * CC + c0 + col;
            *(float4*)(muo + o) = mu;
            *(float4*)(sgo + o) = sg;
            *(float4*)(sco + o) = make_float4(sac, sac, sac, sac);
        }
    } else {
        // correct slow fallback for k2 > K2CAP
        int tx = tid & 15, ty = tid >> 4;
        int col = c0 + tx * 4;
        for (int rr = 0; rr < 4; rr++) {
            int r = ty * 4 + rr;
            int i = i0 + r;
            float tti = 0.f;
            #pragma unroll
            for (int q = 0; q < 8; q++)
                tti += g_ttp[(size_t)q * (BB * WW) + (size_t)b * WW + i];
            float qi = fmaf(vwq, tti, vbq);
            float m = -CUDART_INF_F;
            for (int dt = -k2; dt <= k2; dt++) {
                int j = i + dt;
                if (abs(dt) < k1 || j < 0 || j >= WW) continue;
                float ttj = 0.f;
                #pragma unroll
                for (int q = 0; q < 8; q++)
                    ttj += g_ttp[(size_t)q * (BB * WW) + (size_t)b * WW + j];
                float l = qi * fmaf(vwk, ttj, vbk) * invt;
                m = fmaxf(m, l);
            }
            float4 a = make_float4(0.f, 0.f, 0.f, 0.f);
            float sac = 1.0f / (1.f + 1e-6f);
            if (m == -CUDART_INF_F) {
                float w = sac;
                float4 xi = *(const float4*)(g_Xs + (size_t)(b * WW + i) * CC + col);
                a.x = w * xi.x; a.y = w * xi.y; a.z = w * xi.z; a.w = w * xi.w;
            } else {
                float Z = 0.f;
                for (int dt = -k2; dt <= k2; dt++) {
                    int j = i + dt;
                    if (abs(dt) < k1 || j < 0 || j >= WW) continue;
                    float ttj = 0.f;
                    #pragma unroll
                    for (int q = 0; q < 8; q++)
                        ttj += g_ttp[(size_t)q * (BB * WW) + (size_t)b * WW + j];
                    float l = qi * fmaf(vwk, ttj, vbk) * invt;
                    float e = expf(l - m);
                    Z += e;
                    float4 x = *(const float4*)(g_Xs + (size_t)(b * WW + j) * CC + col);
                    a.x = fmaf(e, x.x, a.x);
                    a.y = fmaf(e, x.y, a.y);
                    a.z = fmaf(e, x.z, a.z);
                    a.w = fmaf(e, x.w, a.w);
                }
                float s = 1.0f / (Z * (1.f + 1e-6f));
                a.x *= s; a.y *= s; a.z *= s; a.w *= s;
            }
            float4 xo = *(const float4*)(g_Xs + (size_t)(b * WW + i) * CC + col);
            float4 xf, mu, sg;
            xf.x = fmaf(vwv, a.x, vbv * sac) + xo.x;
            xf.y = fmaf(vwv, a.y, vbv * sac) + xo.y;
            xf.z = fmaf(vwv, a.z, vbv * sac) + xo.z;
            xf.w = fmaf(vwv, a.w, vbv * sac) + xo.w;
            mu.x = fminf(fmaxf(fmaf(vwmu, xf.x, vbmu), -20.f), 20.f);
            mu.y = fminf(fmaxf(fmaf(vwmu, xf.y, vbmu), -20.f), 20.f);
            mu.z = fminf(fmaxf(fmaf(vwmu, xf.z, vbmu), -20.f), 20.f);
            mu.w = fminf(fmaxf(fmaf(vwmu, xf.w, vbmu), -20.f), 20.f);
            sg.x = softplusf(fmaf(vws, xf.x, vbs)) + 0.1f;
            sg.y = softplusf(fmaf(vws, xf.y, vbs)) + 0.1f;
            sg.z = softplusf(fmaf(vws, xf.z, vbs)) + 0.1f;
            sg.w = softplusf(fmaf(vws, xf.w, vbs)) + 0.1f;
            size_t o = (size_t)(b * WW + i) * CC + c0 + col;
            *(float4*)(muo + o) = mu;
            *(float4*)(sgo + o) = sg;
            *(float4*)(sco + o) = make_float4(sac, sac, sac, sac);
        }
    }
}

// ---------- launch ----------
extern "C" void kernel_launch(void* const* d_in, const int* in_sizes, int n_in,
                              void* d_out, int out_size) {
    const float* X    = (const float*)d_in[0];
    const float* adj  = (const float*)d_in[1];
    const float* lt   = (const float*)d_in[2];
    const float* wq   = (const float*)d_in[3];
    const float* bq   = (const float*)d_in[4];
    const float* wk   = (const float*)d_in[5];
    const float* bk   = (const float*)d_in[6];
    const float* wv   = (const float*)d_in[7];
    const float* bv   = (const float*)d_in[8];
    const float* wmu  = (const float*)d_in[9];
    const float* bmu  = (const float*)d_in[10];
    const float* wsig = (const float*)d_in[11];
    const float* bsig = (const float*)d_in[12];
    const int*   k1p  = (const int*)d_in[13];
    const int*   k2p  = (const int*)d_in[14];
    float* out = (float*)d_out;

    cudaFuncSetAttribute(gemm_kernel,
                         cudaFuncAttributeMaxDynamicSharedMemorySize, SMEM_GEMM);
    cudaFuncSetAttribute(epilogue_kernel,
                         cudaFuncAttributeMaxDynamicSharedMemorySize, SMEM_EPI);

    // order: prep(1), presplitB(2), gemm(3), epilogue(4 = ncu capture slot)
    prep_kernel<<<NXBLK + 128, 256>>>(X, adj);
    dim3 gb(16, 16, BB);
    presplitB_kernel<<<gb, dim3(32, 8)>>>(adj);
    dim3 g2(CC / BN, WW / BM, BB);
    gemm_kernel<<<g2, 256, SMEM_GEMM>>>();
    dim3 g5(CC / CJ, WW / TI, BB);
    epilogue_kernel<<<g5, 256, SMEM_EPI>>>(lt, wq, bq, wk, bk, wv, bv, wmu, bmu, wsig, bsig,
                                           k1p, k2p, out);
}

// round 15
// speedup vs baseline: 1.7052x; 1.0155x over previous
#include <cuda_runtime.h>
#include <cuda_fp16.h>
#include <math_constants.h>
#include <cstdint>

#define BB 16
#define WW 2048
#define CC 512
#define NN (BB*WW*CC)

// ---------- scratch (no allocations allowed) ----------
__device__ float g_Xs[NN];                 // X_spatial [B,W,C] (64 MB)
__device__ float g_ttp[8*BB*WW];           // partial row sums (8 planes)
__device__ float g_degpart[BB*8*CC];       // partial column sums
__device__ uint32_t g_A16[NN/2];           // X fp16x2, k-pair-permuted (32 MB)
__device__ uint32_t g_B16[BB*CC*CC/2];     // norm-adj^T fp16x2, permuted (8 MB)

__device__ __forceinline__ float softplusf(float x) {
    return fmaxf(x, 0.f) + log1pf(expf(-fabsf(x)));
}

__device__ __forceinline__ uint32_t h2_pack(float v0, float v1) {
    __half2 h = __floats2half2_rn(v0, v1);
    return *(uint32_t*)&h;
}

// k-pair permutation within 8-groups: [0,4,1,5,2,6,3,7] so that
// LDS.64 at pos 2*tq yields kpairs (tq, tq+4) = both fragment quarters.
__device__ __forceinline__ uint32_t kperm(uint32_t kp) {
    uint32_t loc = kp & 7u;
    uint32_t pos = (loc < 4u) ? (2u * loc) : (2u * (loc - 4u) + 1u);
    return (kp & ~7u) | pos;
}

__device__ __forceinline__ void mma_fp16(float* c,
                                         uint32_t a0, uint32_t a1, uint32_t a2, uint32_t a3,
                                         uint32_t b0, uint32_t b1) {
    asm volatile(
        "mma.sync.aligned.m16n8k16.row.col.f32.f16.f16.f32 "
        "{%0,%1,%2,%3},{%4,%5,%6,%7},{%8,%9},{%0,%1,%2,%3};\n"
        : "+f"(c[0]), "+f"(c[1]), "+f"(c[2]), "+f"(c[3])
        : "r"(a0), "r"(a1), "r"(a2), "r"(a3), "r"(b0), "r"(b1));
}

// ---------- K1: fused presplitX + deg partial sums ----------
#define NXBLK (NN / 1024)    // 16384 blocks for the X part

__global__ void prep_kernel(const float* __restrict__ X, const float* __restrict__ adj) {
    if (blockIdx.x < NXBLK) {
        size_t i = ((size_t)blockIdx.x * 256 + threadIdx.x) * 4;
        float4 v = *(const float4*)(X + i);
        uint32_t kp = (uint32_t)(i >> 1);       // even kpair index
        uint32_t kp1 = kp + 1;
        size_t grp_base = (i >> 1) & ~7ULL;     // 8-kpair group base
        g_A16[grp_base + (kperm(kp) & 7u)]  = h2_pack(v.x, v.y);
        g_A16[grp_base + (kperm(kp1) & 7u)] = h2_pack(v.z, v.w);
    } else {
        int idx = blockIdx.x - NXBLK;     // 0..127
        int b = idx >> 3, chunk = idx & 7;
        int i0 = chunk * 64;
        const float* A = adj + (size_t)b * CC * CC;
        for (int j = threadIdx.x; j < CC; j += 256) {
            float s = 0.f;
            #pragma unroll 8
            for (int i = 0; i < 64; i++)
                s += fmaxf(A[(size_t)(i0 + i) * CC + j], 0.f);
            g_degpart[(b * 8 + chunk) * CC + j] = s;
        }
    }
}

// ---------- K2: B = transpose(relu(adj)) * invdeg -> fp16 plane (permuted) ----------
__global__ void presplitB_kernel(const float* __restrict__ adj) {
    __shared__ float t[32][33];
    __shared__ float sdeg[32];
    int b = blockIdx.z;
    int i0 = blockIdx.y * 32, j0 = blockIdx.x * 32;
    int tx = threadIdx.x, ty = threadIdx.y;   // (32, 8)
    const float* A = adj + (size_t)b * CC * CC;
    if (ty == 0) {
        float s = 0.f;
        #pragma unroll
        for (int c = 0; c < 8; c++) s += g_degpart[(b * 8 + c) * CC + j0 + tx];
        sdeg[tx] = 1.0f / fmaxf(s, 1e-4f);
    }
    #pragma unroll
    for (int r = 0; r < 4; r++) {
        int il = ty + r * 8;
        t[il][tx] = fmaxf(A[(size_t)(i0 + il) * CC + j0 + tx], 0.f);
    }
    __syncthreads();
    if (tx < 16) {
        #pragma unroll
        for (int r = 0; r < 4; r++) {
            int jl = ty + r * 8;
            int j = j0 + jl;
            float sc = sdeg[jl];
            float v0 = t[2 * tx][jl] * sc;
            float v1 = t[2 * tx + 1][jl] * sc;
            uint32_t kp = (uint32_t)(i0 / 2 + tx);    // kpair index within row
            size_t rowbase = ((size_t)b * CC + j) * (CC / 2);
            g_B16[rowbase + (kp & ~7u) + (kperm(kp) & 7u)] = h2_pack(v0, v1);
        }
    }
}

// ---------- K3: fp16 HMMA GEMM, 3-stage cp.async, LDS.64 fragments ----------
#define BM 128
#define BN 128
#define BK 32
#define KPC 16                 // kpairs per chunk
#define ST 24                  // uint row stride (16 data + 8 pad): bank-perfect LDS.64
#define NCHUNK (CC / BK)       // 16
#define TILE_U (128 * ST)      // uints per tile
#define STAGE_B (TILE_U * 4 * 2)           // A + B, bytes = 24576
#define SMEM_GEMM (3 * STAGE_B)            // 73728

__global__ void __launch_bounds__(256, 2) gemm_kernel() {
    extern __shared__ unsigned char smraw[];
    int b = blockIdx.z, m0 = blockIdx.y * BM, n0 = blockIdx.x * BN;
    int tid = threadIdx.x;
    int lane = tid & 31, wid = tid >> 5;
    int quad = lane >> 2, tq = lane & 3;
    int wm = wid >> 1, wn = wid & 1;

    uint32_t* As[3];
    uint32_t* Bs[3];
    #pragma unroll
    for (int s = 0; s < 3; s++) {
        As[s] = (uint32_t*)(smraw + s * STAGE_B);
        Bs[s] = (uint32_t*)(smraw + s * STAGE_B + TILE_U * 4);
    }

    const uint32_t* Abase = g_A16 + (size_t)(b * WW + m0) * (CC / 2);
    const uint32_t* Bbase = g_B16 + ((size_t)b * CC + n0) * (CC / 2);

    float acc[2][8][4];
    #pragma unroll
    for (int am = 0; am < 2; am++)
        #pragma unroll
        for (int an = 0; an < 8; an++)
            #pragma unroll
            for (int q = 0; q < 4; q++) acc[am][an][q] = 0.f;

    #define LOAD_STAGE(c, s) do { \
        int _kp0 = (c) * KPC; \
        _Pragma("unroll") \
        for (int it = 0; it < 2; it++) { \
            int ch = tid * 2 + it; \
            int row = ch >> 2, c16 = ch & 3; \
            uint32_t dA = (uint32_t)__cvta_generic_to_shared(&As[s][row * ST + c16 * 4]); \
            const uint32_t* sA = Abase + (size_t)row * (CC / 2) + _kp0 + c16 * 4; \
            asm volatile("cp.async.cg.shared.global [%0], [%1], 16;" \
                :: "r"(dA), "l"((unsigned long long)__cvta_generic_to_global((void*)sA)) : "memory"); \
            uint32_t dB = (uint32_t)__cvta_generic_to_shared(&Bs[s][row * ST + c16 * 4]); \
            const uint32_t* sB = Bbase + (size_t)row * (CC / 2) + _kp0 + c16 * 4; \
            asm volatile("cp.async.cg.shared.global [%0], [%1], 16;" \
                :: "r"(dB), "l"((unsigned long long)__cvta_generic_to_global((void*)sB)) : "memory"); \
        } \
    } while(0)

    LOAD_STAGE(0, 0);
    asm volatile("cp.async.commit_group;" ::: "memory");
    LOAD_STAGE(1, 1);
    asm volatile("cp.async.commit_group;" ::: "memory");

    for (int c = 0; c < NCHUNK; c++) {
        int s = c % 3;
        asm volatile("cp.async.wait_group 1;" ::: "memory");
        __syncthreads();
        if (c + 2 < NCHUNK) LOAD_STAGE(c + 2, (c + 2) % 3);
        asm volatile("cp.async.commit_group;" ::: "memory");

        #pragma unroll
        for (int ks = 0; ks < 2; ks++) {
            int kb = ks * 8;
            uint2 aA[2], aB[2];
            #pragma unroll
            for (int am = 0; am < 2; am++) {
                int r0 = wm * 32 + am * 16 + quad;
                aA[am] = *(uint2*)&As[s][r0 * ST + kb + 2 * tq];
                aB[am] = *(uint2*)&As[s][(r0 + 8) * ST + kb + 2 * tq];
            }
            #pragma unroll
            for (int an = 0; an < 8; an++) {
                int c0b = wn * 64 + an * 8 + quad;
                uint2 bb = *(uint2*)&Bs[s][c0b * ST + kb + 2 * tq];
                #pragma unroll
                for (int am = 0; am < 2; am++) {
                    mma_fp16(acc[am][an], aA[am].x, aB[am].x, aA[am].y, aB[am].y,
                             bb.x, bb.y);
                }
            }
        }
    }

    float* outp = g_Xs + (size_t)b * WW * CC;
    int cbase = n0 + wn * 64;
    #pragma unroll
    for (int am = 0; am < 2; am++) {
        int grow = m0 + wm * 32 + am * 16 + quad;
        #pragma unroll
        for (int an = 0; an < 8; an++) {
            int gc = cbase + an * 8 + tq * 2;
            *(float2*)(outp + (size_t)grow * CC + gc) = make_float2(acc[am][an][0], acc[am][an][1]);
            *(float2*)(outp + (size_t)(grow + 8) * CC + gc) = make_float2(acc[am][an][2], acc[am][an][3]);
        }
    }

    // fused partial row sums; deterministic, no atomics
    float rs00 = 0.f, rs01 = 0.f, rs10 = 0.f, rs11 = 0.f;
    #pragma unroll
    for (int an = 0; an < 8; an++) {
        rs00 += acc[0][an][0] + acc[0][an][1];
        rs01 += acc[0][an][2] + acc[0][an][3];
        rs10 += acc[1][an][0] + acc[1][an][1];
        rs11 += acc[1][an][2] + acc[1][an][3];
    }
    #pragma unroll
    for (int o = 1; o <= 2; o <<= 1) {
        rs00 += __shfl_xor_sync(0xffffffffu, rs00, o);
        rs01 += __shfl_xor_sync(0xffffffffu, rs01, o);
        rs10 += __shfl_xor_sync(0xffffffffu, rs10, o);
        rs11 += __shfl_xor_sync(0xffffffffu, rs11, o);
    }
    if (tq == 0) {
        size_t pl = (size_t)(blockIdx.x * 2 + wn) * (BB * WW) + (size_t)b * WW;
        int r0w = m0 + wm * 32 + quad;
        const float inv = 1.0f / CC;
        g_ttp[pl + r0w]      = rs00 * inv;
        g_ttp[pl + r0w + 8]  = rs01 * inv;
        g_ttp[pl + r0w + 16] = rs10 * inv;
        g_ttp[pl + r0w + 24] = rs11 * inv;
    }
    #undef LOAD_STAGE
}

// ---------- K4: fused band-attention + epilogue (diagonal weights) ----------
#define TI 64
#define CJ 64
#define K2CAP 32
#define XR (TI + 2 * K2CAP)     // 128
#define NDTMAX (2 * K2CAP + 1)  // 65
#define SDW 68                  // sD row stride (floats): float4-aligned
#define SDROWS XR               // 128
#define SMEM_EPI ((XR * CJ + SDROWS * SDW + XR + TI) * 4)

// CK1/CK2 >= 0: compile-time band bounds (full unroll). CK1 = -1: runtime.
template<int CK1, int CK2>
__device__ __forceinline__ void epi_body(
    float* sX, float* sD, float* sTT, float* sSac,
    int b, int i0, int c0, int k1r, int k2r,
    float invt, float vwq, float vbq, float vwk, float vbk,
    float vwv, float vbv, float vwmu, float vbmu, float vws, float vbs,
    float* muo, float* sgo, float* sco) {

    const int k1 = (CK1 >= 0) ? CK1 : k1r;
    const int k2 = (CK1 >= 0) ? CK2 : k2r;
    int tid = threadIdx.x;
    int jlo = i0 - k2;
    int nrows = TI + 2 * k2;
    int ndt = 2 * k2 + 1;

    // zero sD
    for (int idx = tid; idx < SDROWS * SDW / 4; idx += 256)
        *(float4*)&sD[idx * 4] = make_float4(0.f, 0.f, 0.f, 0.f);
    // load X window + token window
    for (int idx = tid; idx < nrows * (CJ / 4); idx += 256) {
        int row = idx >> 4;
        int c4 = (idx & 15) * 4;
        int j = jlo + row;
        float4 v = make_float4(0.f, 0.f, 0.f, 0.f);
        if (j >= 0 && j < WW)
            v = *(const float4*)(g_Xs + (size_t)(b * WW + j) * CC + c0 + c4);
        *(float4*)&sX[row * CJ + c4] = v;
    }
    for (int idx = tid; idx < nrows; idx += 256) {
        int j = jlo + idx;
        float s = 0.f;
        if (j >= 0 && j < WW) {
            #pragma unroll
            for (int q = 0; q < 8; q++)
                s += g_ttp[(size_t)q * (BB * WW) + (size_t)b * WW + j];
        }
        sTT[idx] = s;
    }
    __syncthreads();

    int lane = tid & 31, wid = tid >> 5;
    for (int r = wid; r < TI; r += 8) {
        int i = i0 + r;
        float qi = fmaf(vwq, sTT[r + k2], vbq);
        float m = -CUDART_INF_F;
        float lv[3];
        #pragma unroll
        for (int q = 0; q < 3; q++) {
            int p = lane + q * 32;
            lv[q] = -CUDART_INF_F;
            if (p < ndt) {
                int dt = p - k2;
                int j = i + dt;
                bool valid = (abs(dt) >= k1) && (j >= 0) && (j < WW);
                if (valid) lv[q] = qi * fmaf(vwk, sTT[r + p], vbk) * invt;
                m = fmaxf(m, lv[q]);
            }
        }
        #pragma unroll
        for (int o = 16; o; o >>= 1) m = fmaxf(m, __shfl_xor_sync(0xffffffffu, m, o));
        if (m == -CUDART_INF_F) {
            if (lane == 0) {
                sD[(r + k2) * SDW + r] = 1.0f / (1.f + 1e-6f);
                sSac[r] = 1.0f / (1.f + 1e-6f);
            }
        } else {
            float e[3]; float zs = 0.f;
            #pragma unroll
            for (int q = 0; q < 3; q++) {
                int p = lane + q * 32;
                e[q] = (p < ndt) ? expf(lv[q] - m) : 0.f;
                zs += e[q];
            }
            #pragma unroll
            for (int o = 16; o; o >>= 1) zs += __shfl_xor_sync(0xffffffffu, zs, o);
            float invz = 1.0f / zs;
            float s2 = 0.f;
            #pragma unroll
            for (int q = 0; q < 3; q++) { e[q] *= invz; s2 += e[q]; }
            #pragma unroll
            for (int o = 16; o; o >>= 1) s2 += __shfl_xor_sync(0xffffffffu, s2, o);
            float invd = 1.0f / (s2 + 1e-6f);
            #pragma unroll
            for (int q = 0; q < 3; q++) {
                int p = lane + q * 32;
                if (p < ndt) sD[(r + p) * SDW + r] = e[q] * invd;
            }
            if (lane == 0) sSac[r] = s2 * invd;
        }
    }
    __syncthreads();

    // banded weighted sum via diagonal float4 weight reads (zeros mask edges)
    int tx = tid & 15, ty = tid >> 4;
    int col = tx * 4;
    int r0 = ty * 4;
    float4 a0 = make_float4(0.f,0.f,0.f,0.f), a1 = a0, a2 = a0, a3 = a0;
    #define BAND_TAP(t) do { \
        float4 x = *(const float4*)&sX[(r0 + (t)) * CJ + col]; \
        float4 w = *(const float4*)&sD[(r0 + (t)) * SDW + r0]; \
        a0.x = fmaf(w.x, x.x, a0.x); a0.y = fmaf(w.x, x.y, a0.y); \
        a0.z = fmaf(w.x, x.z, a0.z); a0.w = fmaf(w.x, x.w, a0.w); \
        a1.x = fmaf(w.y, x.x, a1.x); a1.y = fmaf(w.y, x.y, a1.y); \
        a1.z = fmaf(w.y, x.z, a1.z); a1.w = fmaf(w.y, x.w, a1.w); \
        a2.x = fmaf(w.z, x.x, a2.x); a2.y = fmaf(w.z, x.y, a2.y); \
        a2.z = fmaf(w.z, x.z, a2.z); a2.w = fmaf(w.z, x.w, a2.w); \
        a3.x = fmaf(w.w, x.x, a3.x); a3.y = fmaf(w.w, x.y, a3.y); \
        a3.z = fmaf(w.w, x.z, a3.z); a3.w = fmaf(w.w, x.w, a3.w); \
    } while(0)
    if (CK1 >= 4 || (CK1 < 0 && k1 >= 4)) {
        #pragma unroll
        for (int t = 0; t <= (CK1 >= 0 ? CK2 - CK1 + 3 : 0) + ((CK1 >= 0) ? 0 : 0); t++) {
            // placeholder; real loops below
            break;
        }
        // segment 1: dt in [-k2, -k1]
        if (CK1 >= 0) {
            #pragma unroll
            for (int t = 0; t <= CK2 - CK1 + 3; t++) BAND_TAP(t);
            #pragma unroll
            for (int t = CK2; t <= CK2 + 3; t++) BAND_TAP(t);
            #pragma unroll
            for (int t = CK2 + CK1; t <= 2 * CK2 + 3; t++) BAND_TAP(t);
        } else {
            for (int t = 0; t <= k2 - k1 + 3; t++) BAND_TAP(t);
            for (int t = k2; t <= k2 + 3; t++) BAND_TAP(t);
            for (int t = k2 + k1; t <= 2 * k2 + 3; t++) BAND_TAP(t);
        }
    } else {
        if (CK1 >= 0) {
            #pragma unroll
            for (int t = 0; t <= 2 * CK2 + 3; t++) BAND_TAP(t);
        } else {
            for (int t = 0; t <= 2 * k2 + 3; t++) BAND_TAP(t);
        }
    }
    #undef BAND_TAP

    float4 av[4] = { a0, a1, a2, a3 };
    #pragma unroll
    for (int rr = 0; rr < 4; rr++) {
        int r = r0 + rr;
        int i = i0 + r;
        float sac = sSac[r];
        float4 xo = *(const float4*)&sX[(r + k2) * CJ + col];
        float4 xf, mu, sg;
        xf.x = fmaf(vwv, av[rr].x, vbv * sac) + xo.x;
        xf.y = fmaf(vwv, av[rr].y, vbv * sac) + xo.y;
        xf.z = fmaf(vwv, av[rr].z, vbv * sac) + xo.z;
        xf.w = fmaf(vwv, av[rr].w, vbv * sac) + xo.w;
        mu.x = fminf(fmaxf(fmaf(vwmu, xf.x, vbmu), -20.f), 20.f);
        mu.y = fminf(fmaxf(fmaf(vwmu, xf.y, vbmu), -20.f), 20.f);
        mu.z = fminf(fmaxf(fmaf(vwmu, xf.z, vbmu), -20.f), 20.f);
        mu.w = fminf(fmaxf(fmaf(vwmu, xf.w, vbmu), -20.f), 20.f);
        sg.x = softplusf(fmaf(vws, xf.x, vbs)) + 0.1f;
        sg.y = softplusf(fmaf(vws, xf.y, vbs)) + 0.1f;
        sg.z = softplusf(fmaf(vws, xf.z, vbs)) + 0.1f;
        sg.w = softplusf(fmaf(vws, xf.w, vbs)) + 0.1f;
        size_t o = (size_t)(b * WW + i) * CC + c0 + col;
        *(float4*)(muo + o) = mu;
        *(float4*)(sgo + o) = sg;
        *(float4*)(sco + o) = make_float4(sac, sac, sac, sac);
    }
}

__global__ __launch_bounds__(256)
void epilogue_kernel(const float* __restrict__ lt,
                     const float* __restrict__ wq, const float* __restrict__ bq,
                     const float* __restrict__ wk, const float* __restrict__ bk,
                     const float* __restrict__ wv, const float* __restrict__ bv,
                     const float* __restrict__ wmu, const float* __restrict__ bmu,
                     const float* __restrict__ wsig, const float* __restrict__ bsig,
                     const int* __restrict__ k1p, const int* __restrict__ k2p,
                     float* __restrict__ out) {
    extern __shared__ float esm[];
    float* sX  = esm;
    float* sD  = esm + XR * CJ;
    float* sTT = sD + SDROWS * SDW;
    float* sSac = sTT + XR;

    int b = blockIdx.z, i0 = blockIdx.y * TI, c0 = blockIdx.x * CJ;
    int k1 = k1p[0], k2 = k2p[0];
    float invt = 1.0f / (softplusf(lt[0]) + 1e-4f);
    float vwq = wq[0], vbq = bq[0], vwk = wk[0], vbk = bk[0];
    float vwv = wv[0], vbv = bv[0];
    float vwmu = wmu[0], vbmu = bmu[0], vws = wsig[0], vbs = bsig[0];
    int tid = threadIdx.x;
    float* muo = out;
    float* sgo = out + (size_t)NN;
    float* sco = out + 2 * (size_t)NN;

    if (k2 <= K2CAP) {
        if (k1 == 20 && k2 == 30) {
            epi_body<20, 30>(sX, sD, sTT, sSac, b, i0, c0, k1, k2,
                             invt, vwq, vbq, vwk, vbk, vwv, vbv, vwmu, vbmu, vws, vbs,
                             muo, sgo, sco);
        } else {
            epi_body<-1, -1>(sX, sD, sTT, sSac, b, i0, c0, k1, k2,
                             invt, vwq, vbq, vwk, vbk, vwv, vbv, vwmu, vbmu, vws, vbs,
                             muo, sgo, sco);
        }
    } else {
        // correct slow fallback for k2 > K2CAP
        int tx = tid & 15, ty = tid >> 4;
        int col = c0 + tx * 4;
        for (int rr = 0; rr < 4; rr++) {
            int r = ty * 4 + rr;
            int i = i0 + r;
            float tti = 0.f;
            #pragma unroll
            for (int q = 0; q < 8; q++)
                tti += g_ttp[(size_t)q * (BB * WW) + (size_t)b * WW + i];
            float qi = fmaf(vwq, tti, vbq);
            float m = -CUDART_INF_F;
            for (int dt = -k2; dt <= k2; dt++) {
                int j = i + dt;
                if (abs(dt) < k1 || j < 0 || j >= WW) continue;
                float ttj = 0.f;
                #pragma unroll
                for (int q = 0; q < 8; q++)
                    ttj += g_ttp[(size_t)q * (BB * WW) + (size_t)b * WW + j];
                float l = qi * fmaf(vwk, ttj, vbk) * invt;
                m = fmaxf(m, l);
            }
            float4 a = make_float4(0.f, 0.f, 0.f, 0.f);
            float sac = 1.0f / (1.f + 1e-6f);
            if (m == -CUDART_INF_F) {
                float w = sac;
                float4 xi = *(const float4*)(g_Xs + (size_t)(b * WW + i) * CC + col);
                a.x = w * xi.x; a.y = w * xi.y; a.z = w * xi.z; a.w = w * xi.w;
            } else {
                float Z = 0.f;
                for (int dt = -k2; dt <= k2; dt++) {
                    int j = i + dt;
                    if (abs(dt) < k1 || j < 0 || j >= WW) continue;
                    float ttj = 0.f;
                    #pragma unroll
                    for (int q = 0; q < 8; q++)
                        ttj += g_ttp[(size_t)q * (BB * WW) + (size_t)b * WW + j];
                    float l = qi * fmaf(vwk, ttj, vbk) * invt;
                    float e = expf(l - m);
                    Z += e;
                    float4 x = *(const float4*)(g_Xs + (size_t)(b * WW + j) * CC + col);
                    a.x = fmaf(e, x.x, a.x);
                    a.y = fmaf(e, x.y, a.y);
                    a.z = fmaf(e, x.z, a.z);
                    a.w = fmaf(e, x.w, a.w);
                }
                float s = 1.0f / (Z * (1.f + 1e-6f));
                a.x *= s; a.y *= s; a.z *= s; a.w *= s;
            }
            float4 xo = *(const float4*)(g_Xs + (size_t)(b * WW + i) * CC + col);
            float4 xf, mu, sg;
            xf.x = fmaf(vwv, a.x, vbv * sac) + xo.x;
            xf.y = fmaf(vwv, a.y, vbv * sac) + xo.y;
            xf.z = fmaf(vwv, a.z, vbv * sac) + xo.z;
            xf.w = fmaf(vwv, a.w, vbv * sac) + xo.w;
            mu.x = fminf(fmaxf(fmaf(vwmu, xf.x, vbmu), -20.f), 20.f);
            mu.y = fminf(fmaxf(fmaf(vwmu, xf.y, vbmu), -20.f), 20.f);
            mu.z = fminf(fmaxf(fmaf(vwmu, xf.z, vbmu), -20.f), 20.f);
            mu.w = fminf(fmaxf(fmaf(vwmu, xf.w, vbmu), -20.f), 20.f);
            sg.x = softplusf(fmaf(vws, xf.x, vbs)) + 0.1f;
            sg.y = softplusf(fmaf(vws, xf.y, vbs)) + 0.1f;
            sg.z = softplusf(fmaf(vws, xf.z, vbs)) + 0.1f;
            sg.w = softplusf(fmaf(vws, xf.w, vbs)) + 0.1f;
            size_t o = (size_t)(b * WW + i) * CC + col;
            *(float4*)(muo + o) = mu;
            *(float4*)(sgo + o) = sg;
            *(float4*)(sco + o) = make_float4(sac, sac, sac, sac);
        }
    }
}

// ---------- launch ----------
extern "C" void kernel_launch(void* const* d_in, const int* in_sizes, int n_in,
                              void* d_out, int out_size) {
    const float* X    = (const float*)d_in[0];
    const float* adj  = (const float*)d_in[1];
    const float* lt   = (const float*)d_in[2];
    const float* wq   = (const float*)d_in[3];
    const float* bq   = (const float*)d_in[4];
    const float* wk   = (const float*)d_in[5];
    const float* bk   = (const float*)d_in[6];
    const float* wv   = (const float*)d_in[7];
    const float* bv   = (const float*)d_in[8];
    const float* wmu  = (const float*)d_in[9];
    const float* bmu  = (const float*)d_in[10];
    const float* wsig = (const float*)d_in[11];
    const float* bsig = (const float*)d_in[12];
    const int*   k1p  = (const int*)d_in[13];
    const int*   k2p  = (const int*)d_in[14];
    float* out = (float*)d_out;

    cudaFuncSetAttribute(gemm_kernel,
                         cudaFuncAttributeMaxDynamicSharedMemorySize, SMEM_GEMM);
    cudaFuncSetAttribute(epilogue_kernel,
                         cudaFuncAttributeMaxDynamicSharedMemorySize, SMEM_EPI);

    // order: prep(1), presplitB(2), gemm(3), epilogue(4 = ncu capture slot)
    prep_kernel<<<NXBLK + 128, 256>>>(X, adj);
    dim3 gb(16, 16, BB);
    presplitB_kernel<<<gb, dim3(32, 8)>>>(adj);
    dim3 g2(CC / BN, WW / BM, BB);
    gemm_kernel<<<g2, 256, SMEM_GEMM>>>();
    dim3 g5(CC / CJ, WW / TI, BB);
    epilogue_kernel<<<g5, 256, SMEM_EPI>>>(lt, wq, bq, wk, bk, wv, bv, wmu, bmu, wsig, bsig,
                                           k1p, k2p, out);
}

// round 17
// speedup vs baseline: 2.0776x; 1.2184x over previous
#include <cuda_runtime.h>
#include <cuda_fp16.h>
#include <math_constants.h>
#include <cstdint>

#define BB 16
#define WW 2048
#define CC 512
#define NN (BB*WW*CC)
#define NTILE 32                  // WW / 64 i-tiles
#define WPAD 128                  // padded jrel rows per tile

// ---------- scratch (no allocations allowed) ----------
__device__ float g_Xs[NN];                 // X_spatial [B,W,C] (64 MB)
__device__ float g_ttp[8*BB*WW];           // partial row sums (8 planes)
__device__ float g_degpart[BB*8*CC];       // partial column sums
__device__ uint32_t g_A16[NN/2];           // X fp16x2, k-pair-permuted (32 MB)
__device__ uint32_t g_B16[BB*CC*CC/2];     // norm-adj^T fp16x2, permuted (8 MB)
__device__ float g_WD[(size_t)BB*NTILE*WPAD*64];  // diag weights [b][tile][jrel][r] (16.8 MB)
__device__ float g_sac[BB*WW];             // sacon scalar per (b,i)

__device__ __forceinline__ float softplusf(float x) {
    return fmaxf(x, 0.f) + log1pf(expf(-fabsf(x)));
}

__device__ __forceinline__ uint32_t h2_pack(float v0, float v1) {
    __half2 h = __floats2half2_rn(v0, v1);
    return *(uint32_t*)&h;
}

// k-pair permutation within 8-groups: [0,4,1,5,2,6,3,7]
__device__ __forceinline__ uint32_t kperm(uint32_t kp) {
    uint32_t loc = kp & 7u;
    uint32_t pos = (loc < 4u) ? (2u * loc) : (2u * (loc - 4u) + 1u);
    return (kp & ~7u) | pos;
}

__device__ __forceinline__ void mma_fp16(float* c,
                                         uint32_t a0, uint32_t a1, uint32_t a2, uint32_t a3,
                                         uint32_t b0, uint32_t b1) {
    asm volatile(
        "mma.sync.aligned.m16n8k16.row.col.f32.f16.f16.f32 "
        "{%0,%1,%2,%3},{%4,%5,%6,%7},{%8,%9},{%0,%1,%2,%3};\n"
        : "+f"(c[0]), "+f"(c[1]), "+f"(c[2]), "+f"(c[3])
        : "r"(a0), "r"(a1), "r"(a2), "r"(a3), "r"(b0), "r"(b1));
}

// ---------- K1: fused presplitX + deg partial sums ----------
#define NXBLK (NN / 1024)

__global__ void prep_kernel(const float* __restrict__ X, const float* __restrict__ adj) {
    if (blockIdx.x < NXBLK) {
        size_t i = ((size_t)blockIdx.x * 256 + threadIdx.x) * 4;
        float4 v = *(const float4*)(X + i);
        uint32_t kp = (uint32_t)(i >> 1);
        uint32_t kp1 = kp + 1;
        size_t grp_base = (i >> 1) & ~7ULL;
        g_A16[grp_base + (kperm(kp) & 7u)]  = h2_pack(v.x, v.y);
        g_A16[grp_base + (kperm(kp1) & 7u)] = h2_pack(v.z, v.w);
    } else {
        int idx = blockIdx.x - NXBLK;
        int b = idx >> 3, chunk = idx & 7;
        int i0 = chunk * 64;
        const float* A = adj + (size_t)b * CC * CC;
        for (int j = threadIdx.x; j < CC; j += 256) {
            float s = 0.f;
            #pragma unroll 8
            for (int i = 0; i < 64; i++)
                s += fmaxf(A[(size_t)(i0 + i) * CC + j], 0.f);
            g_degpart[(b * 8 + chunk) * CC + j] = s;
        }
    }
}

// ---------- K2: B = transpose(relu(adj)) * invdeg -> fp16 plane (permuted) ----------
__global__ void presplitB_kernel(const float* __restrict__ adj) {
    __shared__ float t[32][33];
    __shared__ float sdeg[32];
    int b = blockIdx.z;
    int i0 = blockIdx.y * 32, j0 = blockIdx.x * 32;
    int tx = threadIdx.x, ty = threadIdx.y;
    const float* A = adj + (size_t)b * CC * CC;
    if (ty == 0) {
        float s = 0.f;
        #pragma unroll
        for (int c = 0; c < 8; c++) s += g_degpart[(b * 8 + c) * CC + j0 + tx];
        sdeg[tx] = 1.0f / fmaxf(s, 1e-4f);
    }
    #pragma unroll
    for (int r = 0; r < 4; r++) {
        int il = ty + r * 8;
        t[il][tx] = fmaxf(A[(size_t)(i0 + il) * CC + j0 + tx], 0.f);
    }
    __syncthreads();
    if (tx < 16) {
        #pragma unroll
        for (int r = 0; r < 4; r++) {
            int jl = ty + r * 8;
            int j = j0 + jl;
            float sc = sdeg[jl];
            float v0 = t[2 * tx][jl] * sc;
            float v1 = t[2 * tx + 1][jl] * sc;
            uint32_t kp = (uint32_t)(i0 / 2 + tx);
            size_t rowbase = ((size_t)b * CC + j) * (CC / 2);
            g_B16[rowbase + (kp & ~7u) + (kperm(kp) & 7u)] = h2_pack(v0, v1);
        }
    }
}

// ---------- K3: fp16 HMMA GEMM, 3-stage cp.async, LDS.64 fragments ----------
#define BM 128
#define BN 128
#define BK 32
#define KPC 16
#define ST 24
#define NCHUNK (CC / BK)
#define TILE_U (128 * ST)
#define STAGE_B (TILE_U * 4 * 2)
#define SMEM_GEMM (3 * STAGE_B)

__global__ void __launch_bounds__(256, 2) gemm_kernel() {
    extern __shared__ unsigned char smraw[];
    int b = blockIdx.z, m0 = blockIdx.y * BM, n0 = blockIdx.x * BN;
    int tid = threadIdx.x;
    int lane = tid & 31, wid = tid >> 5;
    int quad = lane >> 2, tq = lane & 3;
    int wm = wid >> 1, wn = wid & 1;

    uint32_t* As[3];
    uint32_t* Bs[3];
    #pragma unroll
    for (int s = 0; s < 3; s++) {
        As[s] = (uint32_t*)(smraw + s * STAGE_B);
        Bs[s] = (uint32_t*)(smraw + s * STAGE_B + TILE_U * 4);
    }

    const uint32_t* Abase = g_A16 + (size_t)(b * WW + m0) * (CC / 2);
    const uint32_t* Bbase = g_B16 + ((size_t)b * CC + n0) * (CC / 2);

    float acc[2][8][4];
    #pragma unroll
    for (int am = 0; am < 2; am++)
        #pragma unroll
        for (int an = 0; an < 8; an++)
            #pragma unroll
            for (int q = 0; q < 4; q++) acc[am][an][q] = 0.f;

    #define LOAD_STAGE(c, s) do { \
        int _kp0 = (c) * KPC; \
        _Pragma("unroll") \
        for (int it = 0; it < 2; it++) { \
            int ch = tid * 2 + it; \
            int row = ch >> 2, c16 = ch & 3; \
            uint32_t dA = (uint32_t)__cvta_generic_to_shared(&As[s][row * ST + c16 * 4]); \
            const uint32_t* sA = Abase + (size_t)row * (CC / 2) + _kp0 + c16 * 4; \
            asm volatile("cp.async.cg.shared.global [%0], [%1], 16;" \
                :: "r"(dA), "l"((unsigned long long)__cvta_generic_to_global((void*)sA)) : "memory"); \
            uint32_t dB = (uint32_t)__cvta_generic_to_shared(&Bs[s][row * ST + c16 * 4]); \
            const uint32_t* sB = Bbase + (size_t)row * (CC / 2) + _kp0 + c16 * 4; \
            asm volatile("cp.async.cg.shared.global [%0], [%1], 16;" \
                :: "r"(dB), "l"((unsigned long long)__cvta_generic_to_global((void*)sB)) : "memory"); \
        } \
    } while(0)

    LOAD_STAGE(0, 0);
    asm volatile("cp.async.commit_group;" ::: "memory");
    LOAD_STAGE(1, 1);
    asm volatile("cp.async.commit_group;" ::: "memory");

    for (int c = 0; c < NCHUNK; c++) {
        int s = c % 3;
        asm volatile("cp.async.wait_group 1;" ::: "memory");
        __syncthreads();
        if (c + 2 < NCHUNK) LOAD_STAGE(c + 2, (c + 2) % 3);
        asm volatile("cp.async.commit_group;" ::: "memory");

        #pragma unroll
        for (int ks = 0; ks < 2; ks++) {
            int kb = ks * 8;
            uint2 aA[2], aB[2];
            #pragma unroll
            for (int am = 0; am < 2; am++) {
                int r0 = wm * 32 + am * 16 + quad;
                aA[am] = *(uint2*)&As[s][r0 * ST + kb + 2 * tq];
                aB[am] = *(uint2*)&As[s][(r0 + 8) * ST + kb + 2 * tq];
            }
            #pragma unroll
            for (int an = 0; an < 8; an++) {
                int c0b = wn * 64 + an * 8 + quad;
                uint2 bb = *(uint2*)&Bs[s][c0b * ST + kb + 2 * tq];
                #pragma unroll
                for (int am = 0; am < 2; am++) {
                    mma_fp16(acc[am][an], aA[am].x, aB[am].x, aA[am].y, aB[am].y,
                             bb.x, bb.y);
                }
            }
        }
    }

    float* outp = g_Xs + (size_t)b * WW * CC;
    int cbase = n0 + wn * 64;
    #pragma unroll
    for (int am = 0; am < 2; am++) {
        int grow = m0 + wm * 32 + am * 16 + quad;
        #pragma unroll
        for (int an = 0; an < 8; an++) {
            int gc = cbase + an * 8 + tq * 2;
            *(float2*)(outp + (size_t)grow * CC + gc) = make_float2(acc[am][an][0], acc[am][an][1]);
            *(float2*)(outp + (size_t)(grow + 8) * CC + gc) = make_float2(acc[am][an][2], acc[am][an][3]);
        }
    }

    // fused partial row sums (token mean partials)
    float rs00 = 0.f, rs01 = 0.f, rs10 = 0.f, rs11 = 0.f;
    #pragma unroll
    for (int an = 0; an < 8; an++) {
        rs00 += acc[0][an][0] + acc[0][an][1];
        rs01 += acc[0][an][2] + acc[0][an][3];
        rs10 += acc[1][an][0] + acc[1][an][1];
        rs11 += acc[1][an][2] + acc[1][an][3];
    }
    #pragma unroll
    for (int o = 1; o <= 2; o <<= 1) {
        rs00 += __shfl_xor_sync(0xffffffffu, rs00, o);
        rs01 += __shfl_xor_sync(0xffffffffu, rs01, o);
        rs10 += __shfl_xor_sync(0xffffffffu, rs10, o);
        rs11 += __shfl_xor_sync(0xffffffffu, rs11, o);
    }
    if (tq == 0) {
        size_t pl = (size_t)(blockIdx.x * 2 + wn) * (BB * WW) + (size_t)b * WW;
        int r0w = m0 + wm * 32 + quad;
        const float inv = 1.0f / CC;
        g_ttp[pl + r0w]      = rs00 * inv;
        g_ttp[pl + r0w + 8]  = rs01 * inv;
        g_ttp[pl + r0w + 16] = rs10 * inv;
        g_ttp[pl + r0w + 24] = rs11 * inv;
    }
    #undef LOAD_STAGE
}

// ---------- K4: attention weights -> diag dense layout + sacon ----------
#define TI 64
#define K2CAP 32
#define IDV (1.0f / (1.f + 1e-6f))

__global__ __launch_bounds__(256)
void weights_kernel(const float* __restrict__ lt,
                    const float* __restrict__ wq, const float* __restrict__ bq,
                    const float* __restrict__ wk, const float* __restrict__ bk,
                    const int* __restrict__ k1p, const int* __restrict__ k2p) {
    int k1 = k1p[0], k2 = k2p[0];
    if (k2 > K2CAP) return;   // fallback path does not use g_WD
    __shared__ float stt[WPAD];
    __shared__ float sm[TI];
    __shared__ float ssc[TI];

    int tile = blockIdx.x, b = blockIdx.y;
    int i0 = tile * TI;
    int jlo = i0 - k2;
    int nrows = TI + 2 * k2;
    int ndt = 2 * k2 + 1;
    float invt = 1.0f / (softplusf(lt[0]) + 1e-4f);
    float vwq = wq[0], vbq = bq[0], vwk = wk[0], vbk = bk[0];
    int tid = threadIdx.x;

    for (int idx = tid; idx < nrows; idx += 256) {
        int j = jlo + idx;
        float s = 0.f;
        if (j >= 0 && j < WW) {
            #pragma unroll
            for (int q = 0; q < 8; q++)
                s += g_ttp[(size_t)q * (BB * WW) + (size_t)b * WW + j];
        }
        stt[idx] = s;
    }
    __syncthreads();

    int lane = tid & 31, wid = tid >> 5;
    for (int r = wid; r < TI; r += 8) {
        int i = i0 + r;
        float qi = fmaf(vwq, stt[r + k2], vbq);
        float m = -CUDART_INF_F;
        float lv[3];
        #pragma unroll
        for (int q = 0; q < 3; q++) {
            int p = lane + q * 32;
            lv[q] = -CUDART_INF_F;
            if (p < ndt) {
                int dt = p - k2;
                int j = i + dt;
                bool valid = (abs(dt) >= k1) && (j >= 0) && (j < WW);
                if (valid) lv[q] = qi * fmaf(vwk, stt[r + p], vbk) * invt;
                m = fmaxf(m, lv[q]);
            }
        }
        #pragma unroll
        for (int o = 16; o; o >>= 1) m = fmaxf(m, __shfl_xor_sync(0xffffffffu, m, o));
        if (m == -CUDART_INF_F) {
            if (lane == 0) {
                sm[r] = m;
                ssc[r] = 0.f;
                g_sac[(size_t)b * WW + i] = IDV;
            }
        } else {
            float e[3]; float zs = 0.f;
            #pragma unroll
            for (int q = 0; q < 3; q++) {
                int p = lane + q * 32;
                e[q] = (p < ndt) ? expf(lv[q] - m) : 0.f;
                zs += e[q];
            }
            #pragma unroll
            for (int o = 16; o; o >>= 1) zs += __shfl_xor_sync(0xffffffffu, zs, o);
            float invz = 1.0f / zs;
            float s2 = 0.f;
            #pragma unroll
            for (int q = 0; q < 3; q++) s2 += e[q] * invz;
            #pragma unroll
            for (int o = 16; o; o >>= 1) s2 += __shfl_xor_sync(0xffffffffu, s2, o);
            float invd = 1.0f / (s2 + 1e-6f);
            if (lane == 0) {
                sm[r] = m;
                ssc[r] = invz * invd;
                g_sac[(size_t)b * WW + i] = s2 * invd;
            }
        }
    }
    __syncthreads();

    // dense diag fill: g_WD[b][tile][jrel][r]
    float* wd = g_WD + ((size_t)(b * NTILE + tile)) * WPAD * 64;
    for (int e = tid; e < nrows * 64; e += 256) {
        int jrel = e >> 6;
        int r = e & 63;
        int dt = jrel - r - k2;
        int i = i0 + r;
        int j = i + dt;
        float m = sm[r];
        float w = 0.f;
        if (m == -CUDART_INF_F) {
            w = (dt == 0) ? IDV : 0.f;
        } else {
            bool valid = (abs(dt) >= k1) && (abs(dt) <= k2) && (j >= 0) && (j < WW);
            if (valid) {
                float qi = fmaf(vwq, stt[r + k2], vbq);
                float kj = fmaf(vwk, stt[jrel], vbk);
                w = expf(qi * kj * invt - m) * ssc[r];
            }
        }
        wd[(size_t)jrel * 64 + r] = w;
    }
}

// ---------- K5: epilogue v2 — no smem, no barriers ----------
#define CJ 64

template<int CK1, int CK2, bool CLAMP>
__device__ __forceinline__ void epi2_body(
    int b, int i0, int c0, int k1r, int k2r,
    float vwv, float vbv, float vwmu, float vbmu, float vws, float vbs,
    float* muo, float* sgo, float* sco) {

    const int k1 = (CK1 >= 0) ? CK1 : k1r;
    const int k2 = (CK1 >= 0) ? CK2 : k2r;
    int tid = threadIdx.x;
    int tx = tid & 15, ty = tid >> 4;
    int col = c0 + tx * 4;
    int r0 = ty * 4;
    int jlo = i0 - k2;

    const float* wbase = g_WD + ((size_t)(b * NTILE + (i0 >> 6))) * WPAD * 64 + r0;
    const float* xbase = g_Xs + (size_t)b * WW * CC + col;

    float4 a0 = make_float4(0.f,0.f,0.f,0.f), a1 = a0, a2 = a0, a3 = a0;

    #define BAND_TAP(t) do { \
        float4 w = *(const float4*)(wbase + (size_t)(r0 + (t)) * 64); \
        int jabs = jlo + r0 + (t); \
        if (CLAMP) jabs = min(max(jabs, 0), WW - 1); \
        float4 x = *(const float4*)(xbase + (size_t)jabs * CC); \
        a0.x = fmaf(w.x, x.x, a0.x); a0.y = fmaf(w.x, x.y, a0.y); \
        a0.z = fmaf(w.x, x.z, a0.z); a0.w = fmaf(w.x, x.w, a0.w); \
        a1.x = fmaf(w.y, x.x, a1.x); a1.y = fmaf(w.y, x.y, a1.y); \
        a1.z = fmaf(w.y, x.z, a1.z); a1.w = fmaf(w.y, x.w, a1.w); \
        a2.x = fmaf(w.z, x.x, a2.x); a2.y = fmaf(w.z, x.y, a2.y); \
        a2.z = fmaf(w.z, x.z, a2.z); a2.w = fmaf(w.z, x.w, a2.w); \
        a3.x = fmaf(w.w, x.x, a3.x); a3.y = fmaf(w.w, x.y, a3.y); \
        a3.z = fmaf(w.w, x.z, a3.z); a3.w = fmaf(w.w, x.w, a3.w); \
    } while(0)

    if (CK1 >= 0) {
        if (CK1 >= 4) {
            #pragma unroll
            for (int t = 0; t <= CK2 - CK1 + 3; t++) BAND_TAP(t);
            #pragma unroll
            for (int t = CK2; t <= CK2 + 3; t++) BAND_TAP(t);
            #pragma unroll
            for (int t = CK2 + CK1; t <= 2 * CK2 + 3; t++) BAND_TAP(t);
        } else {
            #pragma unroll
            for (int t = 0; t <= 2 * CK2 + 3; t++) BAND_TAP(t);
        }
    } else {
        if (k1 >= 4) {
            for (int t = 0; t <= k2 - k1 + 3; t++) BAND_TAP(t);
            for (int t = k2; t <= k2 + 3; t++) BAND_TAP(t);
            for (int t = k2 + k1; t <= 2 * k2 + 3; t++) BAND_TAP(t);
        } else {
            for (int t = 0; t <= 2 * k2 + 3; t++) BAND_TAP(t);
        }
    }
    #undef BAND_TAP

    float4 av[4] = { a0, a1, a2, a3 };
    #pragma unroll
    for (int rr = 0; rr < 4; rr++) {
        int i = i0 + r0 + rr;
        float sac = g_sac[(size_t)b * WW + i];
        float4 xo = *(const float4*)(xbase + (size_t)i * CC);
        float4 xf, mu, sg;
        xf.x = fmaf(vwv, av[rr].x, vbv * sac) + xo.x;
        xf.y = fmaf(vwv, av[rr].y, vbv * sac) + xo.y;
        xf.z = fmaf(vwv, av[rr].z, vbv * sac) + xo.z;
        xf.w = fmaf(vwv, av[rr].w, vbv * sac) + xo.w;
        mu.x = fminf(fmaxf(fmaf(vwmu, xf.x, vbmu), -20.f), 20.f);
        mu.y = fminf(fmaxf(fmaf(vwmu, xf.y, vbmu), -20.f), 20.f);
        mu.z = fminf(fmaxf(fmaf(vwmu, xf.z, vbmu), -20.f), 20.f);
        mu.w = fminf(fmaxf(fmaf(vwmu, xf.w, vbmu), -20.f), 20.f);
        sg.x = softplusf(fmaf(vws, xf.x, vbs)) + 0.1f;
        sg.y = softplusf(fmaf(vws, xf.y, vbs)) + 0.1f;
        sg.z = softplusf(fmaf(vws, xf.z, vbs)) + 0.1f;
        sg.w = softplusf(fmaf(vws, xf.w, vbs)) + 0.1f;
        size_t o = (size_t)(b * WW + i) * CC + col;
        *(float4*)(muo + o) = mu;
        *(float4*)(sgo + o) = sg;
        *(float4*)(sco + o) = make_float4(sac, sac, sac, sac);
    }
}

__global__ __launch_bounds__(256, 4)
void epilogue_kernel(const float* __restrict__ lt,
                     const float* __restrict__ wq, const float* __restrict__ bq,
                     const float* __restrict__ wk, const float* __restrict__ bk,
                     const float* __restrict__ wv, const float* __restrict__ bv,
                     const float* __restrict__ wmu, const float* __restrict__ bmu,
                     const float* __restrict__ wsig, const float* __restrict__ bsig,
                     const int* __restrict__ k1p, const int* __restrict__ k2p,
                     float* __restrict__ out) {
    int b = blockIdx.z, i0 = blockIdx.y * TI, c0 = blockIdx.x * CJ;
    int k1 = k1p[0], k2 = k2p[0];
    float vwv = wv[0], vbv = bv[0];
    float vwmu = wmu[0], vbmu = bmu[0], vws = wsig[0], vbs = bsig[0];
    float* muo = out;
    float* sgo = out + (size_t)NN;
    float* sco = out + 2 * (size_t)NN;

    if (k2 <= K2CAP) {
        bool interior = (i0 - k2 >= 0) && (i0 + TI - 1 + k2 + 3 < WW);
        if (k1 == 20 && k2 == 30) {
            if (interior)
                epi2_body<20, 30, false>(b, i0, c0, k1, k2, vwv, vbv, vwmu, vbmu, vws, vbs, muo, sgo, sco);
            else
                epi2_body<20, 30, true>(b, i0, c0, k1, k2, vwv, vbv, vwmu, vbmu, vws, vbs, muo, sgo, sco);
        } else {
            epi2_body<-1, -1, true>(b, i0, c0, k1, k2, vwv, vbv, vwmu, vbmu, vws, vbs, muo, sgo, sco);
        }
    } else {
        // correct slow fallback for k2 > K2CAP (uses g_ttp, independent of g_WD)
        float invt = 1.0f / (softplusf(lt[0]) + 1e-4f);
        float vwq = wq[0], vbq = bq[0], vwk = wk[0], vbk = bk[0];
        int tid = threadIdx.x;
        int tx = tid & 15, ty = tid >> 4;
        int col = c0 + tx * 4;
        for (int rr = 0; rr < 4; rr++) {
            int r = ty * 4 + rr;
            int i = i0 + r;
            float tti = 0.f;
            #pragma unroll
            for (int q = 0; q < 8; q++)
                tti += g_ttp[(size_t)q * (BB * WW) + (size_t)b * WW + i];
            float qi = fmaf(vwq, tti, vbq);
            float m = -CUDART_INF_F;
            for (int dt = -k2; dt <= k2; dt++) {
                int j = i + dt;
                if (abs(dt) < k1 || j < 0 || j >= WW) continue;
                float ttj = 0.f;
                #pragma unroll
                for (int q = 0; q < 8; q++)
                    ttj += g_ttp[(size_t)q * (BB * WW) + (size_t)b * WW + j];
                float l = qi * fmaf(vwk, ttj, vbk) * invt;
                m = fmaxf(m, l);
            }
            float4 a = make_float4(0.f, 0.f, 0.f, 0.f);
            float sac = IDV;
            if (m == -CUDART_INF_F) {
                float4 xi = *(const float4*)(g_Xs + (size_t)(b * WW + i) * CC + col);
                a.x = sac * xi.x; a.y = sac * xi.y; a.z = sac * xi.z; a.w = sac * xi.w;
            } else {
                float Z = 0.f;
                for (int dt = -k2; dt <= k2; dt++) {
                    int j = i + dt;
                    if (abs(dt) < k1 || j < 0 || j >= WW) continue;
                    float ttj = 0.f;
                    #pragma unroll
                    for (int q = 0; q < 8; q++)
                        ttj += g_ttp[(size_t)q * (BB * WW) + (size_t)b * WW + j];
                    float l = qi * fmaf(vwk, ttj, vbk) * invt;
                    float e = expf(l - m);
                    Z += e;
                    float4 x = *(const float4*)(g_Xs + (size_t)(b * WW + j) * CC + col);
                    a.x = fmaf(e, x.x, a.x);
                    a.y = fmaf(e, x.y, a.y);
                    a.z = fmaf(e, x.z, a.z);
                    a.w = fmaf(e, x.w, a.w);
                }
                float s = 1.0f / (Z * (1.f + 1e-6f));
                a.x *= s; a.y *= s; a.z *= s; a.w *= s;
            }
            float4 xo = *(const float4*)(g_Xs + (size_t)(b * WW + i) * CC + col);
            float4 xf, mu, sg;
            xf.x = fmaf(vwv, a.x, vbv * sac) + xo.x;
            xf.y = fmaf(vwv, a.y, vbv * sac) + xo.y;
            xf.z = fmaf(vwv, a.z, vbv * sac) + xo.z;
            xf.w = fmaf(vwv, a.w, vbv * sac) + xo.w;
            mu.x = fminf(fmaxf(fmaf(vwmu, xf.x, vbmu), -20.f), 20.f);
            mu.y = fminf(fmaxf(fmaf(vwmu, xf.y, vbmu), -20.f), 20.f);
            mu.z = fminf(fmaxf(fmaf(vwmu, xf.z, vbmu), -20.f), 20.f);
            mu.w = fminf(fmaxf(fmaf(vwmu, xf.w, vbmu), -20.f), 20.f);
            sg.x = softplusf(fmaf(vws, xf.x, vbs)) + 0.1f;
            sg.y = softplusf(fmaf(vws, xf.y, vbs)) + 0.1f;
            sg.z = softplusf(fmaf(vws, xf.z, vbs)) + 0.1f;
            sg.w = softplusf(fmaf(vws, xf.w, vbs)) + 0.1f;
            size_t o = (size_t)(b * WW + i) * CC + col;
            *(float4*)(muo + o) = mu;
            *(float4*)(sgo + o) = sg;
            *(float4*)(sco + o) = make_float4(sac, sac, sac, sac);
        }
    }
}

// ---------- launch ----------
extern "C" void kernel_launch(void* const* d_in, const int* in_sizes, int n_in,
                              void* d_out, int out_size) {
    const float* X    = (const float*)d_in[0];
    const float* adj  = (const float*)d_in[1];
    const float* lt   = (const float*)d_in[2];
    const float* wq   = (const float*)d_in[3];
    const float* bq   = (const float*)d_in[4];
    const float* wk   = (const float*)d_in[5];
    const float* bk   = (const float*)d_in[6];
    const float* wv   = (const float*)d_in[7];
    const float* bv   = (const float*)d_in[8];
    const float* wmu  = (const float*)d_in[9];
    const float* bmu  = (const float*)d_in[10];
    const float* wsig = (const float*)d_in[11];
    const float* bsig = (const float*)d_in[12];
    const int*   k1p  = (const int*)d_in[13];
    const int*   k2p  = (const int*)d_in[14];
    float* out = (float*)d_out;

    cudaFuncSetAttribute(gemm_kernel,
                         cudaFuncAttributeMaxDynamicSharedMemorySize, SMEM_GEMM);

    // order: prep(1), presplitB(2), gemm(3), weights(4), epilogue(5)
    prep_kernel<<<NXBLK + 128, 256>>>(X, adj);
    dim3 gb(16, 16, BB);
    presplitB_kernel<<<gb, dim3(32, 8)>>>(adj);
    dim3 g2(CC / BN, WW / BM, BB);
    gemm_kernel<<<g2, 256, SMEM_GEMM>>>();
    dim3 gw(NTILE, BB);
    weights_kernel<<<gw, 256>>>(lt, wq, bq, wk, bk, k1p, k2p);
    dim3 g5(CC / CJ, WW / TI, BB);
    epilogue_kernel<<<g5, 256>>>(lt, wq, bq, wk, bk, wv, bv, wmu, bmu, wsig, bsig,
                                 k1p, k2p, out);
}